// round 7
// baseline (speedup 1.0000x reference)
#include <cuda_runtime.h>
#include <cuda_fp16.h>
#include <cstdint>
#include <cstddef>

#define FULL_MASK 0xFFFFFFFFu

// Problem constants: B=128, N=196, C=768, h=12, e=64, frames=16
// tokens M = 25088 ; b = 8 ; S = 3136 ; bh = 96
static const int M_TOK = 25088;

// ---------------------------------------------------------------------------
// Scratch (allocation-free: __device__ globals)
// ---------------------------------------------------------------------------
__device__ float g_qkv[(size_t)25088 * 2304];   // [tok][3*C]  (q|k|v), q/k ReLU'd
__device__ float g_kv[96 * 64 * 64];            // [bh][e][d]
__device__ float g_ksum[96 * 64];               // [bh][e]
__device__ float g_kvp[7 * 96 * 64 * 64];       // S-split partials
__device__ float g_ksump[7 * 96 * 64];

// fp16-split fragment-ordered tiles.
// A-split: [mb][kt][part(2)][mtile(8)][512B] -> (M/16)*(K/16)*1KB
// B (hi only): [nb][kt][ntile(16)][256B]     -> (N/8)*(K/16)*512B
__device__ uint4 g_a1s[(25088 / 16) * (768 / 16) * 64];   // 77.1 MB (x)
__device__ uint4 g_a2s[(25088 / 16) * (768 / 16) * 64];   // 77.1 MB (attn, by out_kernel)
__device__ uint4 g_b1s[(2304 / 8) * (768 / 16) * 16];     // 3.5 MB (Wqkv)
__device__ uint4 g_b2s[(768 / 8) * (768 / 16) * 16];      // 1.2 MB (Wproj)

// ---------------------------------------------------------------------------
__device__ __forceinline__ uint32_t smem_u32(const void* p) {
    uint32_t r;
    asm("{.reg .u64 t; cvta.to.shared.u64 t, %1; cvt.u32.u64 %0, t;}" : "=r"(r) : "l"(p));
    return r;
}

// Split float2 -> hi f16x2 (return) + residual f16x2 (lo). low half = .x
__device__ __forceinline__ uint32_t split2h(float2 v, uint32_t& lo) {
    __half2 h = __float22half2_rn(v);
    float2 back = __half22float2(h);
    __half2 l = __float22half2_rn(make_float2(v.x - back.x, v.y - back.y));
    lo = *(uint32_t*)&l;
    return *(uint32_t*)&h;
}
__device__ __forceinline__ uint32_t cvt2h(float2 v) {
    __half2 h = __float22half2_rn(v);
    return *(uint32_t*)&h;
}

// mma.sync m16n8k16 fp16: d += a*b (row.col, f32 accum)
__device__ __forceinline__ void mma16(float4& d, uint4 a, uint2 b) {
    asm volatile(
        "mma.sync.aligned.m16n8k16.row.col.f32.f16.f16.f32 "
        "{%0,%1,%2,%3}, {%4,%5,%6,%7}, {%8,%9}, {%0,%1,%2,%3};"
        : "+f"(d.x), "+f"(d.y), "+f"(d.z), "+f"(d.w)
        : "r"(a.x), "r"(a.y), "r"(a.z), "r"(a.w), "r"(b.x), "r"(b.y));
}

// ---------------------------------------------------------------------------
// split_a: fp32 [M][K] -> A-frag tiles (hi+lo fp16), m16n8k16 A layout.
// ---------------------------------------------------------------------------
__global__ __launch_bounds__(256) void split_a(const float* __restrict__ src,
                                               uint4* __restrict__ dst, int K)
{
    const int NKT  = K >> 4;
    const int strip = blockIdx.x;
    const int warp = threadIdx.x >> 5, lane = threadIdx.x & 31;
    const int mb = strip >> 3, mt = strip & 7;
    const int c2 = (lane & 3) * 2;
    const float* row0 = src + (size_t)(strip * 16 + (lane >> 2)) * K;
    const float* row1 = row0 + (size_t)8 * K;
    char* base = (char*)dst;

    for (int kt = warp; kt < NKT; kt += 8) {
        const int kb = kt * 16;
        float2 v00 = *(const float2*)(row0 + kb + c2);
        float2 v10 = *(const float2*)(row1 + kb + c2);
        float2 v01 = *(const float2*)(row0 + kb + c2 + 8);
        float2 v11 = *(const float2*)(row1 + kb + c2 + 8);
        uint32_t l0, l1, l2, l3;
        uint32_t h0 = split2h(v00, l0);
        uint32_t h1 = split2h(v10, l1);
        uint32_t h2 = split2h(v01, l2);
        uint32_t h3 = split2h(v11, l3);
        size_t off = ((size_t)(mb * NKT + kt) << 13) + mt * 512 + lane * 16;
        *(uint4*)(base + off)        = make_uint4(h0, h1, h2, h3);
        *(uint4*)(base + off + 4096) = make_uint4(l0, l1, l2, l3);
    }
}

// ---------------------------------------------------------------------------
// split_b: fp32 [N][K] -> B-frag tiles (hi fp16 only), m16n8k16 B layout.
// ---------------------------------------------------------------------------
__global__ __launch_bounds__(256) void split_b(const float* __restrict__ src,
                                               uint4* __restrict__ dst, int K)
{
    const int NKT  = K >> 4;
    const int strip = blockIdx.x;
    const int warp = threadIdx.x >> 5, lane = threadIdx.x & 31;
    const int nb = strip >> 4, nt = strip & 15;
    const int c2 = (lane & 3) * 2;
    const float* row = src + (size_t)(strip * 8 + (lane >> 2)) * K;
    char* base = (char*)dst;

    for (int kt = warp; kt < NKT; kt += 8) {
        const int kb = kt * 16;
        uint32_t h0 = cvt2h(*(const float2*)(row + kb + c2));
        uint32_t h1 = cvt2h(*(const float2*)(row + kb + c2 + 8));
        size_t off = ((size_t)(nb * NKT + kt) << 12) + nt * 256 + lane * 8;
        *(uint2*)(base + off) = make_uint2(h0, h1);
    }
}

// ---------------------------------------------------------------------------
// fp16 2-term HMMA GEMM on pre-split tiles. Paired-chunk mainloop:
// one __syncthreads per 2 chunks; 64-MMA stretches; cp.async 4-stage ring.
// ---------------------------------------------------------------------------
__global__ __launch_bounds__(256) void gemm_f16(
    const uint4* __restrict__ As, const uint4* __restrict__ Bs, float* __restrict__ C,
    int M, int N, int K, const float* __restrict__ bias, int relu_limit)
{
    __shared__ char smem[4 * 12288];

    const int tid  = threadIdx.x;
    const int lane = tid & 31;
    const int warp = tid >> 5;
    const int mb   = blockIdx.y;
    const int nb   = blockIdx.x;
    const int NKT  = K >> 4;          // 48 (even)
    const uint32_t sb = smem_u32(smem);

    const char* Abase = (const char*)As + ((size_t)mb * NKT << 13);
    const char* Bbase = (const char*)Bs + ((size_t)nb * NKT << 12);

    auto issue = [&](int kc) {
        const char* asrc = Abase + ((size_t)kc << 13);
        const char* bsrc = Bbase + ((size_t)kc << 12);
        const uint32_t dst0 = sb + (kc & 3) * 12288;
#pragma unroll
        for (int i = 0; i < 2; i++) {
            const int c = tid + i * 256;
            asm volatile("cp.async.ca.shared.global [%0], [%1], 16;"
                         :: "r"(dst0 + c * 16), "l"(asrc + c * 16));
        }
        asm volatile("cp.async.ca.shared.global [%0], [%1], 16;"
                     :: "r"(dst0 + 8192 + tid * 16), "l"(bsrc + tid * 16));
        asm volatile("cp.async.commit_group;");
    };

    float4 acc[4][4];
#pragma unroll
    for (int i = 0; i < 4; i++)
#pragma unroll
        for (int j = 0; j < 4; j++) acc[i][j] = make_float4(0.f, 0.f, 0.f, 0.f);

    const int wm = (warp >> 2) * 4;   // A m-tile base (of 8)
    const int wn = (warp & 3) * 4;    // B n-tile base (of 16)

    issue(0); issue(1); issue(2); issue(3);

    auto do_chunk = [&](int kc) {
        const char* st = smem + (kc & 3) * 12288;
        uint4 ah[4], al[4];
        uint2 bh[4];
#pragma unroll
        for (int mt = 0; mt < 4; mt++) {
            ah[mt] = *(const uint4*)(st + (wm + mt) * 512 + lane * 16);
            al[mt] = *(const uint4*)(st + 4096 + (wm + mt) * 512 + lane * 16);
        }
#pragma unroll
        for (int nt = 0; nt < 4; nt++)
            bh[nt] = *(const uint2*)(st + 8192 + (wn + nt) * 256 + lane * 8);
#pragma unroll
        for (int mt = 0; mt < 4; mt++)
#pragma unroll
            for (int nt = 0; nt < 4; nt++) mma16(acc[mt][nt], ah[mt], bh[nt]);
#pragma unroll
        for (int mt = 0; mt < 4; mt++)
#pragma unroll
            for (int nt = 0; nt < 4; nt++) mma16(acc[mt][nt], al[mt], bh[nt]);
    };

#pragma unroll 1
    for (int kc = 0; kc < NKT; kc += 2) {
        if (kc + 2 >= NKT) asm volatile("cp.async.wait_group 0;" ::: "memory");
        else               asm volatile("cp.async.wait_group 2;" ::: "memory");
        __syncthreads();

        do_chunk(kc);
        do_chunk(kc + 1);

        __syncthreads();
        if (kc + 4 < NKT) issue(kc + 4);
        if (kc + 5 < NKT) issue(kc + 5);
    }

    // epilogue: d0:(r,c) d1:(r,c+1) d2:(r+8,c) d3:(r+8,c+1); r=lane/4, c=2*(lane%4)
    const int rbase = mb * 128 + (warp >> 2) * 64 + (lane >> 2);
    const int cbase = nb * 128 + (warp & 3) * 32 + (lane & 3) * 2;
#pragma unroll
    for (int mt = 0; mt < 4; mt++) {
#pragma unroll
        for (int nt = 0; nt < 4; nt++) {
            const int r = rbase + mt * 16;
            const int c = cbase + nt * 8;
            float4 d = acc[mt][nt];
            if (bias) {
                float2 bb = *(const float2*)(bias + c);
                d.x += bb.x; d.y += bb.y; d.z += bb.x; d.w += bb.y;
            }
            if (c < relu_limit) {
                d.x = fmaxf(d.x, 0.f); d.y = fmaxf(d.y, 0.f);
                d.z = fmaxf(d.z, 0.f); d.w = fmaxf(d.w, 0.f);
            }
            *(float2*)(C + (size_t)r * N + c)       = make_float2(d.x, d.y);
            *(float2*)(C + (size_t)(r + 8) * N + c) = make_float2(d.z, d.w);
        }
    }
}

// ---------------------------------------------------------------------------
// KV partial: grid (96, 7); chunk c covers s in [c*448, c*448+448).
// ---------------------------------------------------------------------------
__global__ __launch_bounds__(256) void kv_part()
{
    const int bh = blockIdx.x;
    const int pc = blockIdx.y;
    const int b  = bh / 12;
    const int h  = bh % 12;

    __shared__ float Ks[64][64];
    __shared__ float Vs[64][64];

    const int tid = threadIdx.x;
    const int er  = tid >> 4;
    const int dg  = tid & 15;
    const int sl  = tid >> 2;
    const int ch  = tid & 3;

    float4 acc0 = {0,0,0,0}, acc1 = {0,0,0,0}, acc2 = {0,0,0,0}, acc3 = {0,0,0,0};
    float4 ksum = {0,0,0,0};

    const size_t base_k = (size_t)(b * 3136) * 2304 + 768  + h * 64;
    const size_t base_v = (size_t)(b * 3136) * 2304 + 1536 + h * 64;
    const int s_lo = pc * 448, s_hi = s_lo + 448;

    for (int s0 = s_lo; s0 < s_hi; s0 += 64) {
        const float* kp = g_qkv + base_k + (size_t)(s0 + sl) * 2304 + ch * 16;
        const float* vp = g_qkv + base_v + (size_t)(s0 + sl) * 2304 + ch * 16;
#pragma unroll
        for (int c = 0; c < 4; c++) {
            *(float4*)&Ks[sl][ch * 16 + c * 4] = *(const float4*)(kp + c * 4);
            *(float4*)&Vs[sl][ch * 16 + c * 4] = *(const float4*)(vp + c * 4);
        }
        __syncthreads();

#pragma unroll 8
        for (int s = 0; s < 64; s++) {
            float4 k4 = *(const float4*)&Ks[s][er * 4];
            float4 v4 = *(const float4*)&Vs[s][dg * 4];
            acc0.x += k4.x * v4.x; acc0.y += k4.x * v4.y; acc0.z += k4.x * v4.z; acc0.w += k4.x * v4.w;
            acc1.x += k4.y * v4.x; acc1.y += k4.y * v4.y; acc1.z += k4.y * v4.z; acc1.w += k4.y * v4.w;
            acc2.x += k4.z * v4.x; acc2.y += k4.z * v4.y; acc2.z += k4.z * v4.z; acc2.w += k4.z * v4.w;
            acc3.x += k4.w * v4.x; acc3.y += k4.w * v4.y; acc3.z += k4.w * v4.z; acc3.w += k4.w * v4.w;
            if (dg == 0) {
                ksum.x += k4.x; ksum.y += k4.y; ksum.z += k4.z; ksum.w += k4.w;
            }
        }
        __syncthreads();
    }

    float* kvp = g_kvp + (size_t)(pc * 96 + bh) * 4096;
    *(float4*)&kvp[(er * 4 + 0) * 64 + dg * 4] = acc0;
    *(float4*)&kvp[(er * 4 + 1) * 64 + dg * 4] = acc1;
    *(float4*)&kvp[(er * 4 + 2) * 64 + dg * 4] = acc2;
    *(float4*)&kvp[(er * 4 + 3) * 64 + dg * 4] = acc3;
    if (dg == 0) *(float4*)&g_ksump[(pc * 96 + bh) * 64 + er * 4] = ksum;
}

// Reduce 7 partials (fixed order -> deterministic)
__global__ __launch_bounds__(256) void kv_reduce()
{
    const int bh = blockIdx.x;
    const int tid = threadIdx.x;
#pragma unroll 1
    for (int i = tid * 4; i < 4096; i += 1024) {
        float4 s = make_float4(0.f, 0.f, 0.f, 0.f);
#pragma unroll
        for (int p = 0; p < 7; p++) {
            float4 v = *(const float4*)&g_kvp[(size_t)(p * 96 + bh) * 4096 + i];
            s.x += v.x; s.y += v.y; s.z += v.z; s.w += v.w;
        }
        *(float4*)&g_kv[(size_t)bh * 4096 + i] = s;
    }
    if (tid < 64) {
        float s = 0.f;
#pragma unroll
        for (int p = 0; p < 7; p++) s += g_ksump[(p * 96 + bh) * 64 + tid];
        g_ksum[bh * 64 + tid] = s;
    }
}

// ---------------------------------------------------------------------------
// Output kernel: z = 1/(q.k_sum+eps); attn = (q@kv)*z, written DIRECTLY as
// fp16 hi/lo fragments into g_a2s (A operand for the projection GEMM).
// Thread (warp lane l) owns cols (h*64+2l, h*64+2l+1) of one token == one
// half2 reg slot of the fragment layout.
// ---------------------------------------------------------------------------
__global__ __launch_bounds__(256) void out_kernel()
{
    const int bh    = blockIdx.x;
    const int chunk = blockIdx.y;
    const int b     = bh / 12;
    const int h     = bh % 12;

    __shared__ float KVs[64 * 64];
    __shared__ float ks[64];

    const int tid = threadIdx.x;
    for (int i = tid; i < 1024; i += 256)
        *(float4*)&KVs[i * 4] = *(const float4*)&g_kv[(size_t)bh * 4096 + i * 4];
    if (tid < 16)
        *(float4*)&ks[tid * 4] = *(const float4*)&g_ksum[bh * 64 + tid * 4];
    __syncthreads();

    const int warp = tid >> 5;
    const int lane = tid & 31;
    char* abase = (char*)g_a2s;

    for (int tloc = warp; tloc < 64; tloc += 8) {
        const int s = chunk * 64 + tloc;
        const size_t tok = (size_t)(b * 3136 + s);
        const float* qp = g_qkv + tok * 2304 + h * 64;

        float2 q2 = *(const float2*)(qp + lane * 2);

        float dot = q2.x * ks[lane * 2] + q2.y * ks[lane * 2 + 1];
#pragma unroll
        for (int off = 16; off; off >>= 1) dot += __shfl_xor_sync(FULL_MASK, dot, off);
        const float z = 1.0f / (dot + 1e-4f);

        float2 acc = {0.f, 0.f};
#pragma unroll
        for (int ee = 0; ee < 32; ee++) {
            float qa = __shfl_sync(FULL_MASK, q2.x, ee);
            float qb = __shfl_sync(FULL_MASK, q2.y, ee);
            float2 ka = *(const float2*)&KVs[(2 * ee) * 64 + lane * 2];
            float2 kb = *(const float2*)&KVs[(2 * ee + 1) * 64 + lane * 2];
            acc.x += qa * ka.x + qb * kb.x;
            acc.y += qa * ka.y + qb * kb.y;
        }
        acc.x *= z;
        acc.y *= z;

        // fragment-layout store (hi + residual lo)
        const int mb   = (int)(tok >> 7);
        const int mt   = ((int)tok >> 4) & 7;
        const int mrow = (int)tok & 15;
        const int kt   = h * 4 + (lane >> 3);
        const int L    = (mrow & 7) * 4 + (lane & 3);
        const int r    = ((mrow >> 3) & 1) + 2 * ((lane >> 2) & 1);
        uint32_t lo;
        uint32_t hi = split2h(acc, lo);
        char* p = abase + (((size_t)(mb * 48 + kt)) << 13) + mt * 512 + L * 16 + r * 4;
        *(uint32_t*)p          = hi;
        *(uint32_t*)(p + 4096) = lo;
    }
}

// ---------------------------------------------------------------------------
extern "C" void kernel_launch(void* const* d_in, const int* in_sizes, int n_in,
                              void* d_out, int out_size)
{
    const float* x     = (const float*)d_in[0];
    const float* Wqkv  = (const float*)d_in[1];
    const float* Wproj = (const float*)d_in[2];
    const float* bproj = (const float*)d_in[3];
    float* out = (float*)d_out;

    float* qkv_p;
    uint4 *a1s, *a2s, *b1s, *b2s;
    cudaGetSymbolAddress((void**)&qkv_p, g_qkv);
    cudaGetSymbolAddress((void**)&a1s, g_a1s);
    cudaGetSymbolAddress((void**)&a2s, g_a2s);
    cudaGetSymbolAddress((void**)&b1s, g_b1s);
    cudaGetSymbolAddress((void**)&b2s, g_b2s);

    // 0) pre-split weights + input into fp16 fragment tiles
    split_b<<<2304 / 8, 256>>>(Wqkv,  b1s, 768);
    split_b<<<768 / 8, 256>>>(Wproj, b2s, 768);
    split_a<<<M_TOK / 16, 256>>>(x, a1s, 768);

    // 1) qkv = x @ Wqkv^T  (fused ReLU on q,k cols < 1536)
    gemm_f16<<<dim3(2304 / 128, M_TOK / 128), 256>>>(
        a1s, b1s, qkv_p, M_TOK, 2304, 768, nullptr, 1536);

    // 2) kv and k_sum per (b,h): S-split partials + deterministic reduce
    kv_part<<<dim3(96, 7), 256>>>();
    kv_reduce<<<96, 256>>>();

    // 3) normalized q @ kv -> fp16 fragments (GEMM2's A operand)
    out_kernel<<<dim3(96, 49), 256>>>();

    // 4) out = attn @ Wproj^T + bproj
    gemm_f16<<<dim3(768 / 128, M_TOK / 128), 256>>>(
        a2s, b2s, out, M_TOK, 768, 768, bproj, 0);
}

// round 8
// speedup vs baseline: 1.2119x; 1.2119x over previous
#include <cuda_runtime.h>
#include <cuda_fp16.h>
#include <cstdint>
#include <cstddef>

#define FULL_MASK 0xFFFFFFFFu

// Problem constants: B=128, N=196, C=768, h=12, e=64, frames=16
// tokens M = 25088 ; b = 8 ; S = 3136 ; bh = 96
static const int M_TOK = 25088;

// ---------------------------------------------------------------------------
// Scratch (allocation-free: __device__ globals)
// ---------------------------------------------------------------------------
__device__ float g_qkv[(size_t)25088 * 2304];   // [tok][3*C]  (q|k|v), q/k ReLU'd
__device__ float g_kv[96 * 64 * 64];            // [bh][e][d]
__device__ float g_ksum[96 * 64];               // [bh][e]
__device__ float g_kvp[7 * 96 * 64 * 64];       // S-split partials
__device__ float g_ksump[7 * 96 * 64];

// fp16-split fragment-ordered tiles.
// A-split: [mb][kt][part(2)][mtile(8)][512B] -> (M/16)*(K/16)*1KB
// B (hi only): [nb][kt][ntile(16)][256B]     -> (N/8)*(K/16)*512B
__device__ uint4 g_a1s[(25088 / 16) * (768 / 16) * 64];   // 77.1 MB (x)
__device__ uint4 g_a2s[(25088 / 16) * (768 / 16) * 64];   // 77.1 MB (attn, by out_kernel)
__device__ uint4 g_b1s[(2304 / 8) * (768 / 16) * 16];     // 3.5 MB (Wqkv)
__device__ uint4 g_b2s[(768 / 8) * (768 / 16) * 16];      // 1.2 MB (Wproj)

// ---------------------------------------------------------------------------
__device__ __forceinline__ uint32_t smem_u32(const void* p) {
    uint32_t r;
    asm("{.reg .u64 t; cvta.to.shared.u64 t, %1; cvt.u32.u64 %0, t;}" : "=r"(r) : "l"(p));
    return r;
}

// Split float2 -> hi f16x2 (return) + residual f16x2 (lo). low half = .x
__device__ __forceinline__ uint32_t split2h(float2 v, uint32_t& lo) {
    __half2 h = __float22half2_rn(v);
    float2 back = __half22float2(h);
    __half2 l = __float22half2_rn(make_float2(v.x - back.x, v.y - back.y));
    lo = *(uint32_t*)&l;
    return *(uint32_t*)&h;
}
__device__ __forceinline__ uint32_t cvt2h(float2 v) {
    __half2 h = __float22half2_rn(v);
    return *(uint32_t*)&h;
}

// mma.sync m16n8k16 fp16: d += a*b (row.col, f32 accum)
__device__ __forceinline__ void mma16(float4& d, uint4 a, uint2 b) {
    asm volatile(
        "mma.sync.aligned.m16n8k16.row.col.f32.f16.f16.f32 "
        "{%0,%1,%2,%3}, {%4,%5,%6,%7}, {%8,%9}, {%0,%1,%2,%3};"
        : "+f"(d.x), "+f"(d.y), "+f"(d.z), "+f"(d.w)
        : "r"(a.x), "r"(a.y), "r"(a.z), "r"(a.w), "r"(b.x), "r"(b.y));
}

// ---------------------------------------------------------------------------
// split_a: fp32 [M][K] -> A-frag tiles (hi+lo fp16), m16n8k16 A layout.
// ---------------------------------------------------------------------------
__global__ __launch_bounds__(256) void split_a(const float* __restrict__ src,
                                               uint4* __restrict__ dst, int K)
{
    const int NKT  = K >> 4;
    const int strip = blockIdx.x;
    const int warp = threadIdx.x >> 5, lane = threadIdx.x & 31;
    const int mb = strip >> 3, mt = strip & 7;
    const int c2 = (lane & 3) * 2;
    const float* row0 = src + (size_t)(strip * 16 + (lane >> 2)) * K;
    const float* row1 = row0 + (size_t)8 * K;
    char* base = (char*)dst;

    for (int kt = warp; kt < NKT; kt += 8) {
        const int kb = kt * 16;
        float2 v00 = *(const float2*)(row0 + kb + c2);
        float2 v10 = *(const float2*)(row1 + kb + c2);
        float2 v01 = *(const float2*)(row0 + kb + c2 + 8);
        float2 v11 = *(const float2*)(row1 + kb + c2 + 8);
        uint32_t l0, l1, l2, l3;
        uint32_t h0 = split2h(v00, l0);
        uint32_t h1 = split2h(v10, l1);
        uint32_t h2 = split2h(v01, l2);
        uint32_t h3 = split2h(v11, l3);
        size_t off = ((size_t)(mb * NKT + kt) << 13) + mt * 512 + lane * 16;
        *(uint4*)(base + off)        = make_uint4(h0, h1, h2, h3);
        *(uint4*)(base + off + 4096) = make_uint4(l0, l1, l2, l3);
    }
}

// ---------------------------------------------------------------------------
// split_b: fp32 [N][K] -> B-frag tiles (hi fp16 only), m16n8k16 B layout.
// ---------------------------------------------------------------------------
__global__ __launch_bounds__(256) void split_b(const float* __restrict__ src,
                                               uint4* __restrict__ dst, int K)
{
    const int NKT  = K >> 4;
    const int strip = blockIdx.x;
    const int warp = threadIdx.x >> 5, lane = threadIdx.x & 31;
    const int nb = strip >> 4, nt = strip & 15;
    const int c2 = (lane & 3) * 2;
    const float* row = src + (size_t)(strip * 8 + (lane >> 2)) * K;
    char* base = (char*)dst;

    for (int kt = warp; kt < NKT; kt += 8) {
        const int kb = kt * 16;
        uint32_t h0 = cvt2h(*(const float2*)(row + kb + c2));
        uint32_t h1 = cvt2h(*(const float2*)(row + kb + c2 + 8));
        size_t off = ((size_t)(nb * NKT + kt) << 12) + nt * 256 + lane * 8;
        *(uint2*)(base + off) = make_uint2(h0, h1);
    }
}

// ---------------------------------------------------------------------------
// fp16 2-term HMMA GEMM on pre-split tiles (R6 mainloop, regs capped for
// 2 CTAs/SM). 256 threads, 128x128 tile, BK=16, 4-stage cp.async ring.
// ---------------------------------------------------------------------------
__global__ __launch_bounds__(256, 2) void gemm_f16(
    const uint4* __restrict__ As, const uint4* __restrict__ Bs, float* __restrict__ C,
    int M, int N, int K, const float* __restrict__ bias, int relu_limit)
{
    __shared__ char smem[4 * 12288];

    const int tid  = threadIdx.x;
    const int lane = tid & 31;
    const int warp = tid >> 5;
    const int mb   = blockIdx.y;
    const int nb   = blockIdx.x;
    const int NKT  = K >> 4;
    const uint32_t sb = smem_u32(smem);

    const char* Abase = (const char*)As + ((size_t)mb * NKT << 13);
    const char* Bbase = (const char*)Bs + ((size_t)nb * NKT << 12);

    auto issue = [&](int kc) {
        const char* asrc = Abase + ((size_t)kc << 13);
        const char* bsrc = Bbase + ((size_t)kc << 12);
        const uint32_t dst0 = sb + (kc & 3) * 12288;
#pragma unroll
        for (int i = 0; i < 2; i++) {
            const int c = tid + i * 256;
            asm volatile("cp.async.ca.shared.global [%0], [%1], 16;"
                         :: "r"(dst0 + c * 16), "l"(asrc + c * 16));
        }
        asm volatile("cp.async.ca.shared.global [%0], [%1], 16;"
                     :: "r"(dst0 + 8192 + tid * 16), "l"(bsrc + tid * 16));
        asm volatile("cp.async.commit_group;");
    };

    float4 acc[4][4];
#pragma unroll
    for (int i = 0; i < 4; i++)
#pragma unroll
        for (int j = 0; j < 4; j++) acc[i][j] = make_float4(0.f, 0.f, 0.f, 0.f);

    const int wm = (warp >> 2) * 4;   // A m-tile base (of 8)
    const int wn = (warp & 3) * 4;    // B n-tile base (of 16)

    issue(0); issue(1); issue(2);

#pragma unroll 1
    for (int kc = 0; kc < NKT; kc++) {
        const int remain = NKT - 1 - kc;
        if (remain >= 2)      asm volatile("cp.async.wait_group 2;" ::: "memory");
        else if (remain == 1) asm volatile("cp.async.wait_group 1;" ::: "memory");
        else                  asm volatile("cp.async.wait_group 0;" ::: "memory");
        __syncthreads();

        const char* st = smem + (kc & 3) * 12288;

        uint4 ah[4], al[4];
        uint2 bh[4];
#pragma unroll
        for (int mt = 0; mt < 4; mt++) {
            ah[mt] = *(const uint4*)(st + (wm + mt) * 512 + lane * 16);
            al[mt] = *(const uint4*)(st + 4096 + (wm + mt) * 512 + lane * 16);
        }
#pragma unroll
        for (int nt = 0; nt < 4; nt++)
            bh[nt] = *(const uint2*)(st + 8192 + (wn + nt) * 256 + lane * 8);

        if (kc + 3 < NKT) issue(kc + 3);

#pragma unroll
        for (int mt = 0; mt < 4; mt++)
#pragma unroll
            for (int nt = 0; nt < 4; nt++) mma16(acc[mt][nt], ah[mt], bh[nt]);
#pragma unroll
        for (int mt = 0; mt < 4; mt++)
#pragma unroll
            for (int nt = 0; nt < 4; nt++) mma16(acc[mt][nt], al[mt], bh[nt]);
    }

    // epilogue: d0:(r,c) d1:(r,c+1) d2:(r+8,c) d3:(r+8,c+1); r=lane/4, c=2*(lane%4)
    const int rbase = mb * 128 + (warp >> 2) * 64 + (lane >> 2);
    const int cbase = nb * 128 + (warp & 3) * 32 + (lane & 3) * 2;
#pragma unroll
    for (int mt = 0; mt < 4; mt++) {
#pragma unroll
        for (int nt = 0; nt < 4; nt++) {
            const int r = rbase + mt * 16;
            const int c = cbase + nt * 8;
            float4 d = acc[mt][nt];
            if (bias) {
                float2 bb = *(const float2*)(bias + c);
                d.x += bb.x; d.y += bb.y; d.z += bb.x; d.w += bb.y;
            }
            if (c < relu_limit) {
                d.x = fmaxf(d.x, 0.f); d.y = fmaxf(d.y, 0.f);
                d.z = fmaxf(d.z, 0.f); d.w = fmaxf(d.w, 0.f);
            }
            *(float2*)(C + (size_t)r * N + c)       = make_float2(d.x, d.y);
            *(float2*)(C + (size_t)(r + 8) * N + c) = make_float2(d.z, d.w);
        }
    }
}

// ---------------------------------------------------------------------------
// KV partial: grid (96, 7); chunk c covers s in [c*448, c*448+448).
// ---------------------------------------------------------------------------
__global__ __launch_bounds__(256) void kv_part()
{
    const int bh = blockIdx.x;
    const int pc = blockIdx.y;
    const int b  = bh / 12;
    const int h  = bh % 12;

    __shared__ float Ks[64][64];
    __shared__ float Vs[64][64];

    const int tid = threadIdx.x;
    const int er  = tid >> 4;
    const int dg  = tid & 15;
    const int sl  = tid >> 2;
    const int ch  = tid & 3;

    float4 acc0 = {0,0,0,0}, acc1 = {0,0,0,0}, acc2 = {0,0,0,0}, acc3 = {0,0,0,0};
    float4 ksum = {0,0,0,0};

    const size_t base_k = (size_t)(b * 3136) * 2304 + 768  + h * 64;
    const size_t base_v = (size_t)(b * 3136) * 2304 + 1536 + h * 64;
    const int s_lo = pc * 448, s_hi = s_lo + 448;

    for (int s0 = s_lo; s0 < s_hi; s0 += 64) {
        const float* kp = g_qkv + base_k + (size_t)(s0 + sl) * 2304 + ch * 16;
        const float* vp = g_qkv + base_v + (size_t)(s0 + sl) * 2304 + ch * 16;
#pragma unroll
        for (int c = 0; c < 4; c++) {
            *(float4*)&Ks[sl][ch * 16 + c * 4] = *(const float4*)(kp + c * 4);
            *(float4*)&Vs[sl][ch * 16 + c * 4] = *(const float4*)(vp + c * 4);
        }
        __syncthreads();

#pragma unroll 8
        for (int s = 0; s < 64; s++) {
            float4 k4 = *(const float4*)&Ks[s][er * 4];
            float4 v4 = *(const float4*)&Vs[s][dg * 4];
            acc0.x += k4.x * v4.x; acc0.y += k4.x * v4.y; acc0.z += k4.x * v4.z; acc0.w += k4.x * v4.w;
            acc1.x += k4.y * v4.x; acc1.y += k4.y * v4.y; acc1.z += k4.y * v4.z; acc1.w += k4.y * v4.w;
            acc2.x += k4.z * v4.x; acc2.y += k4.z * v4.y; acc2.z += k4.z * v4.z; acc2.w += k4.z * v4.w;
            acc3.x += k4.w * v4.x; acc3.y += k4.w * v4.y; acc3.z += k4.w * v4.z; acc3.w += k4.w * v4.w;
            if (dg == 0) {
                ksum.x += k4.x; ksum.y += k4.y; ksum.z += k4.z; ksum.w += k4.w;
            }
        }
        __syncthreads();
    }

    float* kvp = g_kvp + (size_t)(pc * 96 + bh) * 4096;
    *(float4*)&kvp[(er * 4 + 0) * 64 + dg * 4] = acc0;
    *(float4*)&kvp[(er * 4 + 1) * 64 + dg * 4] = acc1;
    *(float4*)&kvp[(er * 4 + 2) * 64 + dg * 4] = acc2;
    *(float4*)&kvp[(er * 4 + 3) * 64 + dg * 4] = acc3;
    if (dg == 0) *(float4*)&g_ksump[(pc * 96 + bh) * 64 + er * 4] = ksum;
}

// Reduce 7 partials (fixed order -> deterministic)
__global__ __launch_bounds__(256) void kv_reduce()
{
    const int bh = blockIdx.x;
    const int tid = threadIdx.x;
#pragma unroll 1
    for (int i = tid * 4; i < 4096; i += 1024) {
        float4 s = make_float4(0.f, 0.f, 0.f, 0.f);
#pragma unroll
        for (int p = 0; p < 7; p++) {
            float4 v = *(const float4*)&g_kvp[(size_t)(p * 96 + bh) * 4096 + i];
            s.x += v.x; s.y += v.y; s.z += v.z; s.w += v.w;
        }
        *(float4*)&g_kv[(size_t)bh * 4096 + i] = s;
    }
    if (tid < 64) {
        float s = 0.f;
#pragma unroll
        for (int p = 0; p < 7; p++) s += g_ksump[(p * 96 + bh) * 64 + tid];
        g_ksum[bh * 64 + tid] = s;
    }
}

// ---------------------------------------------------------------------------
// Output kernel: z = 1/(q.k_sum+eps); attn = (q@kv)*z, written DIRECTLY as
// fp16 hi/lo fragments into g_a2s (A operand for the projection GEMM).
// ---------------------------------------------------------------------------
__global__ __launch_bounds__(256) void out_kernel()
{
    const int bh    = blockIdx.x;
    const int chunk = blockIdx.y;
    const int b     = bh / 12;
    const int h     = bh % 12;

    __shared__ float KVs[64 * 64];
    __shared__ float ks[64];

    const int tid = threadIdx.x;
    for (int i = tid; i < 1024; i += 256)
        *(float4*)&KVs[i * 4] = *(const float4*)&g_kv[(size_t)bh * 4096 + i * 4];
    if (tid < 16)
        *(float4*)&ks[tid * 4] = *(const float4*)&g_ksum[bh * 64 + tid * 4];
    __syncthreads();

    const int warp = tid >> 5;
    const int lane = tid & 31;
    char* abase = (char*)g_a2s;

    for (int tloc = warp; tloc < 64; tloc += 8) {
        const int s = chunk * 64 + tloc;
        const size_t tok = (size_t)(b * 3136 + s);
        const float* qp = g_qkv + tok * 2304 + h * 64;

        float2 q2 = *(const float2*)(qp + lane * 2);

        float dot = q2.x * ks[lane * 2] + q2.y * ks[lane * 2 + 1];
#pragma unroll
        for (int off = 16; off; off >>= 1) dot += __shfl_xor_sync(FULL_MASK, dot, off);
        const float z = 1.0f / (dot + 1e-4f);

        float2 acc = {0.f, 0.f};
#pragma unroll
        for (int ee = 0; ee < 32; ee++) {
            float qa = __shfl_sync(FULL_MASK, q2.x, ee);
            float qb = __shfl_sync(FULL_MASK, q2.y, ee);
            float2 ka = *(const float2*)&KVs[(2 * ee) * 64 + lane * 2];
            float2 kb = *(const float2*)&KVs[(2 * ee + 1) * 64 + lane * 2];
            acc.x += qa * ka.x + qb * kb.x;
            acc.y += qa * ka.y + qb * kb.y;
        }
        acc.x *= z;
        acc.y *= z;

        // fragment-layout store (hi + residual lo)
        const int mb   = (int)(tok >> 7);
        const int mt   = ((int)tok >> 4) & 7;
        const int mrow = (int)tok & 15;
        const int kt   = h * 4 + (lane >> 3);
        const int L    = (mrow & 7) * 4 + (lane & 3);
        const int r    = ((mrow >> 3) & 1) + 2 * ((lane >> 2) & 1);
        uint32_t lo;
        uint32_t hi = split2h(acc, lo);
        char* p = abase + (((size_t)(mb * 48 + kt)) << 13) + mt * 512 + L * 16 + r * 4;
        *(uint32_t*)p          = hi;
        *(uint32_t*)(p + 4096) = lo;
    }
}

// ---------------------------------------------------------------------------
extern "C" void kernel_launch(void* const* d_in, const int* in_sizes, int n_in,
                              void* d_out, int out_size)
{
    const float* x     = (const float*)d_in[0];
    const float* Wqkv  = (const float*)d_in[1];
    const float* Wproj = (const float*)d_in[2];
    const float* bproj = (const float*)d_in[3];
    float* out = (float*)d_out;

    float* qkv_p;
    uint4 *a1s, *a2s, *b1s, *b2s;
    cudaGetSymbolAddress((void**)&qkv_p, g_qkv);
    cudaGetSymbolAddress((void**)&a1s, g_a1s);
    cudaGetSymbolAddress((void**)&a2s, g_a2s);
    cudaGetSymbolAddress((void**)&b1s, g_b1s);
    cudaGetSymbolAddress((void**)&b2s, g_b2s);

    // 0) pre-split weights + input into fp16 fragment tiles
    split_b<<<2304 / 8, 256>>>(Wqkv,  b1s, 768);
    split_b<<<768 / 8, 256>>>(Wproj, b2s, 768);
    split_a<<<M_TOK / 16, 256>>>(x, a1s, 768);

    // 1) qkv = x @ Wqkv^T  (fused ReLU on q,k cols < 1536)
    gemm_f16<<<dim3(2304 / 128, M_TOK / 128), 256>>>(
        a1s, b1s, qkv_p, M_TOK, 2304, 768, nullptr, 1536);

    // 2) kv and k_sum per (b,h): S-split partials + deterministic reduce
    kv_part<<<dim3(96, 7), 256>>>();
    kv_reduce<<<96, 256>>>();

    // 3) normalized q @ kv -> fp16 fragments (GEMM2's A operand)
    out_kernel<<<dim3(96, 49), 256>>>();

    // 4) out = attn @ Wproj^T + bproj
    gemm_f16<<<dim3(768 / 128, M_TOK / 128), 256>>>(
        a2s, b2s, out, M_TOK, 768, 768, bproj, 0);
}

// round 9
// speedup vs baseline: 1.2280x; 1.0133x over previous
#include <cuda_runtime.h>
#include <cuda_fp16.h>
#include <cstdint>
#include <cstddef>

#define FULL_MASK 0xFFFFFFFFu

// Problem constants: B=128, N=196, C=768, h=12, e=64, frames=16
// tokens M = 25088 ; b = 8 ; S = 3136 ; bh = 96
static const int M_TOK = 25088;

// ---------------------------------------------------------------------------
// Scratch (allocation-free: __device__ globals)
// ---------------------------------------------------------------------------
__device__ __half g_qkv[(size_t)25088 * 2304]; // [tok][3*C] (q|k|v) fp16, q/k ReLU'd
__device__ float g_kv[96 * 64 * 64];            // [bh][e][d]
__device__ float g_ksum[96 * 64];               // [bh][e]
__device__ float g_kvp[7 * 96 * 64 * 64];       // S-split partials
__device__ float g_ksump[7 * 96 * 64];

// fp16-split fragment-ordered tiles.
// A-split: [mb][kt][part(2)][mtile(8)][512B] -> (M/16)*(K/16)*1KB
// B (hi only): [nb][kt][ntile(16)][256B]     -> (N/8)*(K/16)*512B
__device__ uint4 g_a1s[(25088 / 16) * (768 / 16) * 64];   // 77.1 MB (x)
__device__ uint4 g_a2s[(25088 / 16) * (768 / 16) * 64];   // 77.1 MB (attn, by out_kernel)
__device__ uint4 g_b1s[(2304 / 8) * (768 / 16) * 16];     // 3.5 MB (Wqkv)
__device__ uint4 g_b2s[(768 / 8) * (768 / 16) * 16];      // 1.2 MB (Wproj)

// ---------------------------------------------------------------------------
__device__ __forceinline__ uint32_t smem_u32(const void* p) {
    uint32_t r;
    asm("{.reg .u64 t; cvta.to.shared.u64 t, %1; cvt.u32.u64 %0, t;}" : "=r"(r) : "l"(p));
    return r;
}

// Split float2 -> hi f16x2 (return) + residual f16x2 (lo). low half = .x
__device__ __forceinline__ uint32_t split2h(float2 v, uint32_t& lo) {
    __half2 h = __float22half2_rn(v);
    float2 back = __half22float2(h);
    __half2 l = __float22half2_rn(make_float2(v.x - back.x, v.y - back.y));
    lo = *(uint32_t*)&l;
    return *(uint32_t*)&h;
}
__device__ __forceinline__ uint32_t cvt2h(float2 v) {
    __half2 h = __float22half2_rn(v);
    return *(uint32_t*)&h;
}

// mma.sync m16n8k16 fp16: d += a*b (row.col, f32 accum)
__device__ __forceinline__ void mma16(float4& d, uint4 a, uint2 b) {
    asm volatile(
        "mma.sync.aligned.m16n8k16.row.col.f32.f16.f16.f32 "
        "{%0,%1,%2,%3}, {%4,%5,%6,%7}, {%8,%9}, {%0,%1,%2,%3};"
        : "+f"(d.x), "+f"(d.y), "+f"(d.z), "+f"(d.w)
        : "r"(a.x), "r"(a.y), "r"(a.z), "r"(a.w), "r"(b.x), "r"(b.y));
}

// ---------------------------------------------------------------------------
// split_a: fp32 [M][K] -> A-frag tiles (hi+lo fp16), m16n8k16 A layout.
// ---------------------------------------------------------------------------
__global__ __launch_bounds__(256) void split_a(const float* __restrict__ src,
                                               uint4* __restrict__ dst, int K)
{
    const int NKT  = K >> 4;
    const int strip = blockIdx.x;
    const int warp = threadIdx.x >> 5, lane = threadIdx.x & 31;
    const int mb = strip >> 3, mt = strip & 7;
    const int c2 = (lane & 3) * 2;
    const float* row0 = src + (size_t)(strip * 16 + (lane >> 2)) * K;
    const float* row1 = row0 + (size_t)8 * K;
    char* base = (char*)dst;

    for (int kt = warp; kt < NKT; kt += 8) {
        const int kb = kt * 16;
        float2 v00 = *(const float2*)(row0 + kb + c2);
        float2 v10 = *(const float2*)(row1 + kb + c2);
        float2 v01 = *(const float2*)(row0 + kb + c2 + 8);
        float2 v11 = *(const float2*)(row1 + kb + c2 + 8);
        uint32_t l0, l1, l2, l3;
        uint32_t h0 = split2h(v00, l0);
        uint32_t h1 = split2h(v10, l1);
        uint32_t h2 = split2h(v01, l2);
        uint32_t h3 = split2h(v11, l3);
        size_t off = ((size_t)(mb * NKT + kt) << 13) + mt * 512 + lane * 16;
        *(uint4*)(base + off)        = make_uint4(h0, h1, h2, h3);
        *(uint4*)(base + off + 4096) = make_uint4(l0, l1, l2, l3);
    }
}

// ---------------------------------------------------------------------------
// split_b: fp32 [N][K] -> B-frag tiles (hi fp16 only), m16n8k16 B layout.
// ---------------------------------------------------------------------------
__global__ __launch_bounds__(256) void split_b(const float* __restrict__ src,
                                               uint4* __restrict__ dst, int K)
{
    const int NKT  = K >> 4;
    const int strip = blockIdx.x;
    const int warp = threadIdx.x >> 5, lane = threadIdx.x & 31;
    const int nb = strip >> 4, nt = strip & 15;
    const int c2 = (lane & 3) * 2;
    const float* row = src + (size_t)(strip * 8 + (lane >> 2)) * K;
    char* base = (char*)dst;

    for (int kt = warp; kt < NKT; kt += 8) {
        const int kb = kt * 16;
        uint32_t h0 = cvt2h(*(const float2*)(row + kb + c2));
        uint32_t h1 = cvt2h(*(const float2*)(row + kb + c2 + 8));
        size_t off = ((size_t)(nb * NKT + kt) << 12) + nt * 256 + lane * 8;
        *(uint2*)(base + off) = make_uint2(h0, h1);
    }
}

// ---------------------------------------------------------------------------
// fp16 2-term HMMA GEMM on pre-split tiles. 256 threads, 128x128 tile, BK=16,
// 4-stage cp.async ring, 2 CTAs/SM. Output: half (Ch, ReLU<relu_limit) or
// fp32 (C, +bias).
// ---------------------------------------------------------------------------
__global__ __launch_bounds__(256, 2) void gemm_f16(
    const uint4* __restrict__ As, const uint4* __restrict__ Bs,
    float* __restrict__ C, __half* __restrict__ Ch,
    int M, int N, int K, const float* __restrict__ bias, int relu_limit)
{
    __shared__ char smem[4 * 12288];

    const int tid  = threadIdx.x;
    const int lane = tid & 31;
    const int warp = tid >> 5;
    const int mb   = blockIdx.y;
    const int nb   = blockIdx.x;
    const int NKT  = K >> 4;
    const uint32_t sb = smem_u32(smem);

    const char* Abase = (const char*)As + ((size_t)mb * NKT << 13);
    const char* Bbase = (const char*)Bs + ((size_t)nb * NKT << 12);

    auto issue = [&](int kc) {
        const char* asrc = Abase + ((size_t)kc << 13);
        const char* bsrc = Bbase + ((size_t)kc << 12);
        const uint32_t dst0 = sb + (kc & 3) * 12288;
#pragma unroll
        for (int i = 0; i < 2; i++) {
            const int c = tid + i * 256;
            asm volatile("cp.async.ca.shared.global [%0], [%1], 16;"
                         :: "r"(dst0 + c * 16), "l"(asrc + c * 16));
        }
        asm volatile("cp.async.ca.shared.global [%0], [%1], 16;"
                     :: "r"(dst0 + 8192 + tid * 16), "l"(bsrc + tid * 16));
        asm volatile("cp.async.commit_group;");
    };

    float4 acc[4][4];
#pragma unroll
    for (int i = 0; i < 4; i++)
#pragma unroll
        for (int j = 0; j < 4; j++) acc[i][j] = make_float4(0.f, 0.f, 0.f, 0.f);

    const int wm = (warp >> 2) * 4;   // A m-tile base (of 8)
    const int wn = (warp & 3) * 4;    // B n-tile base (of 16)

    issue(0); issue(1); issue(2);

#pragma unroll 1
    for (int kc = 0; kc < NKT; kc++) {
        const int remain = NKT - 1 - kc;
        if (remain >= 2)      asm volatile("cp.async.wait_group 2;" ::: "memory");
        else if (remain == 1) asm volatile("cp.async.wait_group 1;" ::: "memory");
        else                  asm volatile("cp.async.wait_group 0;" ::: "memory");
        __syncthreads();

        const char* st = smem + (kc & 3) * 12288;

        uint4 ah[4], al[4];
        uint2 bh[4];
#pragma unroll
        for (int mt = 0; mt < 4; mt++) {
            ah[mt] = *(const uint4*)(st + (wm + mt) * 512 + lane * 16);
            al[mt] = *(const uint4*)(st + 4096 + (wm + mt) * 512 + lane * 16);
        }
#pragma unroll
        for (int nt = 0; nt < 4; nt++)
            bh[nt] = *(const uint2*)(st + 8192 + (wn + nt) * 256 + lane * 8);

        if (kc + 3 < NKT) issue(kc + 3);

#pragma unroll
        for (int mt = 0; mt < 4; mt++)
#pragma unroll
            for (int nt = 0; nt < 4; nt++) mma16(acc[mt][nt], ah[mt], bh[nt]);
#pragma unroll
        for (int mt = 0; mt < 4; mt++)
#pragma unroll
            for (int nt = 0; nt < 4; nt++) mma16(acc[mt][nt], al[mt], bh[nt]);
    }

    // epilogue: d0:(r,c) d1:(r,c+1) d2:(r+8,c) d3:(r+8,c+1); r=lane/4, c=2*(lane%4)
    const int rbase = mb * 128 + (warp >> 2) * 64 + (lane >> 2);
    const int cbase = nb * 128 + (warp & 3) * 32 + (lane & 3) * 2;
#pragma unroll
    for (int mt = 0; mt < 4; mt++) {
#pragma unroll
        for (int nt = 0; nt < 4; nt++) {
            const int r = rbase + mt * 16;
            const int c = cbase + nt * 8;
            float4 d = acc[mt][nt];
            if (Ch) {
                if (c < relu_limit) {
                    d.x = fmaxf(d.x, 0.f); d.y = fmaxf(d.y, 0.f);
                    d.z = fmaxf(d.z, 0.f); d.w = fmaxf(d.w, 0.f);
                }
                *(__half2*)(Ch + (size_t)r * N + c) =
                    __float22half2_rn(make_float2(d.x, d.y));
                *(__half2*)(Ch + (size_t)(r + 8) * N + c) =
                    __float22half2_rn(make_float2(d.z, d.w));
            } else {
                if (bias) {
                    float2 bb = *(const float2*)(bias + c);
                    d.x += bb.x; d.y += bb.y; d.z += bb.x; d.w += bb.y;
                }
                *(float2*)(C + (size_t)r * N + c)       = make_float2(d.x, d.y);
                *(float2*)(C + (size_t)(r + 8) * N + c) = make_float2(d.z, d.w);
            }
        }
    }
}

// ---------------------------------------------------------------------------
// KV partial: grid (96, 7); chunk c covers s in [c*448, c*448+448).
// k,v read as fp16, accumulated in fp32.
// ---------------------------------------------------------------------------
__global__ __launch_bounds__(256) void kv_part()
{
    const int bh = blockIdx.x;
    const int pc = blockIdx.y;
    const int b  = bh / 12;
    const int h  = bh % 12;

    __shared__ float Ks[64][64];
    __shared__ float Vs[64][64];

    const int tid = threadIdx.x;
    const int er  = tid >> 4;
    const int dg  = tid & 15;
    const int sl  = tid >> 2;    // 0..63 loader row
    const int ch  = tid & 3;     // 0..3, 16 halves each

    float4 acc0 = {0,0,0,0}, acc1 = {0,0,0,0}, acc2 = {0,0,0,0}, acc3 = {0,0,0,0};
    float4 ksum = {0,0,0,0};

    const size_t base_k = (size_t)(b * 3136) * 2304 + 768  + h * 64;
    const size_t base_v = (size_t)(b * 3136) * 2304 + 1536 + h * 64;
    const int s_lo = pc * 448, s_hi = s_lo + 448;

    for (int s0 = s_lo; s0 < s_hi; s0 += 64) {
        const __half* kp = g_qkv + base_k + (size_t)(s0 + sl) * 2304 + ch * 16;
        const __half* vp = g_qkv + base_v + (size_t)(s0 + sl) * 2304 + ch * 16;
#pragma unroll
        for (int c = 0; c < 2; c++) {
            uint4 kr = *(const uint4*)(kp + c * 8);
            uint4 vr = *(const uint4*)(vp + c * 8);
            float2 f;
            f = __half22float2(*(__half2*)&kr.x); Ks[sl][ch*16 + c*8 + 0] = f.x; Ks[sl][ch*16 + c*8 + 1] = f.y;
            f = __half22float2(*(__half2*)&kr.y); Ks[sl][ch*16 + c*8 + 2] = f.x; Ks[sl][ch*16 + c*8 + 3] = f.y;
            f = __half22float2(*(__half2*)&kr.z); Ks[sl][ch*16 + c*8 + 4] = f.x; Ks[sl][ch*16 + c*8 + 5] = f.y;
            f = __half22float2(*(__half2*)&kr.w); Ks[sl][ch*16 + c*8 + 6] = f.x; Ks[sl][ch*16 + c*8 + 7] = f.y;
            f = __half22float2(*(__half2*)&vr.x); Vs[sl][ch*16 + c*8 + 0] = f.x; Vs[sl][ch*16 + c*8 + 1] = f.y;
            f = __half22float2(*(__half2*)&vr.y); Vs[sl][ch*16 + c*8 + 2] = f.x; Vs[sl][ch*16 + c*8 + 3] = f.y;
            f = __half22float2(*(__half2*)&vr.z); Vs[sl][ch*16 + c*8 + 4] = f.x; Vs[sl][ch*16 + c*8 + 5] = f.y;
            f = __half22float2(*(__half2*)&vr.w); Vs[sl][ch*16 + c*8 + 6] = f.x; Vs[sl][ch*16 + c*8 + 7] = f.y;
        }
        __syncthreads();

#pragma unroll 8
        for (int s = 0; s < 64; s++) {
            float4 k4 = *(const float4*)&Ks[s][er * 4];
            float4 v4 = *(const float4*)&Vs[s][dg * 4];
            acc0.x += k4.x * v4.x; acc0.y += k4.x * v4.y; acc0.z += k4.x * v4.z; acc0.w += k4.x * v4.w;
            acc1.x += k4.y * v4.x; acc1.y += k4.y * v4.y; acc1.z += k4.y * v4.z; acc1.w += k4.y * v4.w;
            acc2.x += k4.z * v4.x; acc2.y += k4.z * v4.y; acc2.z += k4.z * v4.z; acc2.w += k4.z * v4.w;
            acc3.x += k4.w * v4.x; acc3.y += k4.w * v4.y; acc3.z += k4.w * v4.z; acc3.w += k4.w * v4.w;
            if (dg == 0) {
                ksum.x += k4.x; ksum.y += k4.y; ksum.z += k4.z; ksum.w += k4.w;
            }
        }
        __syncthreads();
    }

    float* kvp = g_kvp + (size_t)(pc * 96 + bh) * 4096;
    *(float4*)&kvp[(er * 4 + 0) * 64 + dg * 4] = acc0;
    *(float4*)&kvp[(er * 4 + 1) * 64 + dg * 4] = acc1;
    *(float4*)&kvp[(er * 4 + 2) * 64 + dg * 4] = acc2;
    *(float4*)&kvp[(er * 4 + 3) * 64 + dg * 4] = acc3;
    if (dg == 0) *(float4*)&g_ksump[(pc * 96 + bh) * 64 + er * 4] = ksum;
}

// Reduce 7 partials (fixed order -> deterministic)
__global__ __launch_bounds__(256) void kv_reduce()
{
    const int bh = blockIdx.x;
    const int tid = threadIdx.x;
#pragma unroll 1
    for (int i = tid * 4; i < 4096; i += 1024) {
        float4 s = make_float4(0.f, 0.f, 0.f, 0.f);
#pragma unroll
        for (int p = 0; p < 7; p++) {
            float4 v = *(const float4*)&g_kvp[(size_t)(p * 96 + bh) * 4096 + i];
            s.x += v.x; s.y += v.y; s.z += v.z; s.w += v.w;
        }
        *(float4*)&g_kv[(size_t)bh * 4096 + i] = s;
    }
    if (tid < 64) {
        float s = 0.f;
#pragma unroll
        for (int p = 0; p < 7; p++) s += g_ksump[(p * 96 + bh) * 64 + tid];
        g_ksum[bh * 64 + tid] = s;
    }
}

// ---------------------------------------------------------------------------
// Output kernel: z = 1/(q.k_sum+eps); attn = (q@kv)*z, written DIRECTLY as
// fp16 hi/lo fragments into g_a2s (A operand for the projection GEMM).
// ---------------------------------------------------------------------------
__global__ __launch_bounds__(256) void out_kernel()
{
    const int bh    = blockIdx.x;
    const int chunk = blockIdx.y;
    const int b     = bh / 12;
    const int h     = bh % 12;

    __shared__ float KVs[64 * 64];
    __shared__ float ks[64];

    const int tid = threadIdx.x;
    for (int i = tid; i < 1024; i += 256)
        *(float4*)&KVs[i * 4] = *(const float4*)&g_kv[(size_t)bh * 4096 + i * 4];
    if (tid < 16)
        *(float4*)&ks[tid * 4] = *(const float4*)&g_ksum[bh * 64 + tid * 4];
    __syncthreads();

    const int warp = tid >> 5;
    const int lane = tid & 31;
    char* abase = (char*)g_a2s;

    for (int tloc = warp; tloc < 64; tloc += 8) {
        const int s = chunk * 64 + tloc;
        const size_t tok = (size_t)(b * 3136 + s);
        const __half* qp = g_qkv + tok * 2304 + h * 64;

        float2 q2 = __half22float2(*(const __half2*)(qp + lane * 2));

        float dot = q2.x * ks[lane * 2] + q2.y * ks[lane * 2 + 1];
#pragma unroll
        for (int off = 16; off; off >>= 1) dot += __shfl_xor_sync(FULL_MASK, dot, off);
        const float z = 1.0f / (dot + 1e-4f);

        float2 acc = {0.f, 0.f};
#pragma unroll
        for (int ee = 0; ee < 32; ee++) {
            float qa = __shfl_sync(FULL_MASK, q2.x, ee);
            float qb = __shfl_sync(FULL_MASK, q2.y, ee);
            float2 ka = *(const float2*)&KVs[(2 * ee) * 64 + lane * 2];
            float2 kb = *(const float2*)&KVs[(2 * ee + 1) * 64 + lane * 2];
            acc.x += qa * ka.x + qb * kb.x;
            acc.y += qa * ka.y + qb * kb.y;
        }
        acc.x *= z;
        acc.y *= z;

        // fragment-layout store (hi + residual lo)
        const int mb   = (int)(tok >> 7);
        const int mt   = ((int)tok >> 4) & 7;
        const int mrow = (int)tok & 15;
        const int kt   = h * 4 + (lane >> 3);
        const int L    = (mrow & 7) * 4 + (lane & 3);
        const int r    = ((mrow >> 3) & 1) + 2 * ((lane >> 2) & 1);
        uint32_t lo;
        uint32_t hi = split2h(acc, lo);
        char* p = abase + (((size_t)(mb * 48 + kt)) << 13) + mt * 512 + L * 16 + r * 4;
        *(uint32_t*)p          = hi;
        *(uint32_t*)(p + 4096) = lo;
    }
}

// ---------------------------------------------------------------------------
extern "C" void kernel_launch(void* const* d_in, const int* in_sizes, int n_in,
                              void* d_out, int out_size)
{
    const float* x     = (const float*)d_in[0];
    const float* Wqkv  = (const float*)d_in[1];
    const float* Wproj = (const float*)d_in[2];
    const float* bproj = (const float*)d_in[3];
    float* out = (float*)d_out;

    __half* qkv_p;
    uint4 *a1s, *a2s, *b1s, *b2s;
    cudaGetSymbolAddress((void**)&qkv_p, g_qkv);
    cudaGetSymbolAddress((void**)&a1s, g_a1s);
    cudaGetSymbolAddress((void**)&a2s, g_a2s);
    cudaGetSymbolAddress((void**)&b1s, g_b1s);
    cudaGetSymbolAddress((void**)&b2s, g_b2s);

    // 0) pre-split weights + input into fp16 fragment tiles
    split_b<<<2304 / 8, 256>>>(Wqkv,  b1s, 768);
    split_b<<<768 / 8, 256>>>(Wproj, b2s, 768);
    split_a<<<M_TOK / 16, 256>>>(x, a1s, 768);

    // 1) qkv = x @ Wqkv^T -> fp16 (fused ReLU on q,k cols < 1536)
    gemm_f16<<<dim3(2304 / 128, M_TOK / 128), 256>>>(
        a1s, b1s, nullptr, qkv_p, M_TOK, 2304, 768, nullptr, 1536);

    // 2) kv and k_sum per (b,h): S-split partials + deterministic reduce
    kv_part<<<dim3(96, 7), 256>>>();
    kv_reduce<<<96, 256>>>();

    // 3) normalized q @ kv -> fp16 fragments (GEMM2's A operand)
    out_kernel<<<dim3(96, 49), 256>>>();

    // 4) out = attn @ Wproj^T + bproj (fp32 out)
    gemm_f16<<<dim3(768 / 128, M_TOK / 128), 256>>>(
        a2s, b2s, out, nullptr, M_TOK, 768, 768, bproj, 0);
}

// round 10
// speedup vs baseline: 1.5431x; 1.2566x over previous
#include <cuda_runtime.h>
#include <cuda_fp16.h>
#include <cstdint>
#include <cstddef>

#define FULL_MASK 0xFFFFFFFFu

// Problem constants: B=128, N=196, C=768, h=12, e=64, frames=16
// tokens M = 25088 ; b = 8 ; S = 3136 ; bh = 96
static const int M_TOK = 25088;

// ---------------------------------------------------------------------------
// Scratch (allocation-free: __device__ globals)
// ---------------------------------------------------------------------------
__device__ __half g_qkv[(size_t)25088 * 2304]; // [tok][3*C] (q|k|v) fp16, q/k ReLU'd
__device__ float g_ksum[96 * 64];               // [bh][e]
__device__ float g_kvp[7 * 96 * 64 * 64];       // S-split partials
__device__ float g_ksump[7 * 96 * 64];
__device__ uint2 g_kvfrag[96 * 2048];           // [bh][part(2)][kc(4)][nt(8)][lane(32)] uint2

// fp16-split fragment-ordered tiles.
// A-split: [mb][kt][part(2)][mtile(8)][512B] -> (M/16)*(K/16)*1KB
// B (hi only): [nb][kt][ntile(16)][256B]     -> (N/8)*(K/16)*512B
__device__ uint4 g_a1s[(25088 / 16) * (768 / 16) * 64];   // 77.1 MB (x)
__device__ uint4 g_a2s[(25088 / 16) * (768 / 16) * 64];   // 77.1 MB (attn, by vo_gemm)
__device__ uint4 g_b1s[(2304 / 8) * (768 / 16) * 16];     // 3.5 MB (Wqkv)
__device__ uint4 g_b2s[(768 / 8) * (768 / 16) * 16];      // 1.2 MB (Wproj)

// ---------------------------------------------------------------------------
__device__ __forceinline__ uint32_t smem_u32(const void* p) {
    uint32_t r;
    asm("{.reg .u64 t; cvta.to.shared.u64 t, %1; cvt.u32.u64 %0, t;}" : "=r"(r) : "l"(p));
    return r;
}

// Split float2 -> hi f16x2 (return) + residual f16x2 (lo). low half = .x
__device__ __forceinline__ uint32_t split2h(float2 v, uint32_t& lo) {
    __half2 h = __float22half2_rn(v);
    float2 back = __half22float2(h);
    __half2 l = __float22half2_rn(make_float2(v.x - back.x, v.y - back.y));
    lo = *(uint32_t*)&l;
    return *(uint32_t*)&h;
}
__device__ __forceinline__ uint32_t cvt2h(float2 v) {
    __half2 h = __float22half2_rn(v);
    return *(uint32_t*)&h;
}

// mma.sync m16n8k16 fp16: d += a*b (row.col, f32 accum)
__device__ __forceinline__ void mma16(float4& d, uint4 a, uint2 b) {
    asm volatile(
        "mma.sync.aligned.m16n8k16.row.col.f32.f16.f16.f32 "
        "{%0,%1,%2,%3}, {%4,%5,%6,%7}, {%8,%9}, {%0,%1,%2,%3};"
        : "+f"(d.x), "+f"(d.y), "+f"(d.z), "+f"(d.w)
        : "r"(a.x), "r"(a.y), "r"(a.z), "r"(a.w), "r"(b.x), "r"(b.y));
}

// ---------------------------------------------------------------------------
// split_a: fp32 [M][K] -> A-frag tiles (hi+lo fp16), m16n8k16 A layout.
// ---------------------------------------------------------------------------
__global__ __launch_bounds__(256) void split_a(const float* __restrict__ src,
                                               uint4* __restrict__ dst, int K)
{
    const int NKT  = K >> 4;
    const int strip = blockIdx.x;
    const int warp = threadIdx.x >> 5, lane = threadIdx.x & 31;
    const int mb = strip >> 3, mt = strip & 7;
    const int c2 = (lane & 3) * 2;
    const float* row0 = src + (size_t)(strip * 16 + (lane >> 2)) * K;
    const float* row1 = row0 + (size_t)8 * K;
    char* base = (char*)dst;

    for (int kt = warp; kt < NKT; kt += 8) {
        const int kb = kt * 16;
        float2 v00 = *(const float2*)(row0 + kb + c2);
        float2 v10 = *(const float2*)(row1 + kb + c2);
        float2 v01 = *(const float2*)(row0 + kb + c2 + 8);
        float2 v11 = *(const float2*)(row1 + kb + c2 + 8);
        uint32_t l0, l1, l2, l3;
        uint32_t h0 = split2h(v00, l0);
        uint32_t h1 = split2h(v10, l1);
        uint32_t h2 = split2h(v01, l2);
        uint32_t h3 = split2h(v11, l3);
        size_t off = ((size_t)(mb * NKT + kt) << 13) + mt * 512 + lane * 16;
        *(uint4*)(base + off)        = make_uint4(h0, h1, h2, h3);
        *(uint4*)(base + off + 4096) = make_uint4(l0, l1, l2, l3);
    }
}

// ---------------------------------------------------------------------------
// split_b: fp32 [N][K] -> B-frag tiles (hi fp16 only), m16n8k16 B layout.
// ---------------------------------------------------------------------------
__global__ __launch_bounds__(256) void split_b(const float* __restrict__ src,
                                               uint4* __restrict__ dst, int K)
{
    const int NKT  = K >> 4;
    const int strip = blockIdx.x;
    const int warp = threadIdx.x >> 5, lane = threadIdx.x & 31;
    const int nb = strip >> 4, nt = strip & 15;
    const int c2 = (lane & 3) * 2;
    const float* row = src + (size_t)(strip * 8 + (lane >> 2)) * K;
    char* base = (char*)dst;

    for (int kt = warp; kt < NKT; kt += 8) {
        const int kb = kt * 16;
        uint32_t h0 = cvt2h(*(const float2*)(row + kb + c2));
        uint32_t h1 = cvt2h(*(const float2*)(row + kb + c2 + 8));
        size_t off = ((size_t)(nb * NKT + kt) << 12) + nt * 256 + lane * 8;
        *(uint2*)(base + off) = make_uint2(h0, h1);
    }
}

// ---------------------------------------------------------------------------
// fp16 2-term HMMA GEMM on pre-split tiles. 256 threads, 128x128 tile, BK=16,
// 4-stage cp.async ring, 2 CTAs/SM. Output: half (Ch, ReLU<relu_limit) or
// fp32 (C, +bias).
// ---------------------------------------------------------------------------
__global__ __launch_bounds__(256, 2) void gemm_f16(
    const uint4* __restrict__ As, const uint4* __restrict__ Bs,
    float* __restrict__ C, __half* __restrict__ Ch,
    int M, int N, int K, const float* __restrict__ bias, int relu_limit)
{
    __shared__ char smem[4 * 12288];

    const int tid  = threadIdx.x;
    const int lane = tid & 31;
    const int warp = tid >> 5;
    const int mb   = blockIdx.y;
    const int nb   = blockIdx.x;
    const int NKT  = K >> 4;
    const uint32_t sb = smem_u32(smem);

    const char* Abase = (const char*)As + ((size_t)mb * NKT << 13);
    const char* Bbase = (const char*)Bs + ((size_t)nb * NKT << 12);

    auto issue = [&](int kc) {
        const char* asrc = Abase + ((size_t)kc << 13);
        const char* bsrc = Bbase + ((size_t)kc << 12);
        const uint32_t dst0 = sb + (kc & 3) * 12288;
#pragma unroll
        for (int i = 0; i < 2; i++) {
            const int c = tid + i * 256;
            asm volatile("cp.async.ca.shared.global [%0], [%1], 16;"
                         :: "r"(dst0 + c * 16), "l"(asrc + c * 16));
        }
        asm volatile("cp.async.ca.shared.global [%0], [%1], 16;"
                     :: "r"(dst0 + 8192 + tid * 16), "l"(bsrc + tid * 16));
        asm volatile("cp.async.commit_group;");
    };

    float4 acc[4][4];
#pragma unroll
    for (int i = 0; i < 4; i++)
#pragma unroll
        for (int j = 0; j < 4; j++) acc[i][j] = make_float4(0.f, 0.f, 0.f, 0.f);

    const int wm = (warp >> 2) * 4;   // A m-tile base (of 8)
    const int wn = (warp & 3) * 4;    // B n-tile base (of 16)

    issue(0); issue(1); issue(2);

#pragma unroll 1
    for (int kc = 0; kc < NKT; kc++) {
        const int remain = NKT - 1 - kc;
        if (remain >= 2)      asm volatile("cp.async.wait_group 2;" ::: "memory");
        else if (remain == 1) asm volatile("cp.async.wait_group 1;" ::: "memory");
        else                  asm volatile("cp.async.wait_group 0;" ::: "memory");
        __syncthreads();

        const char* st = smem + (kc & 3) * 12288;

        uint4 ah[4], al[4];
        uint2 bh[4];
#pragma unroll
        for (int mt = 0; mt < 4; mt++) {
            ah[mt] = *(const uint4*)(st + (wm + mt) * 512 + lane * 16);
            al[mt] = *(const uint4*)(st + 4096 + (wm + mt) * 512 + lane * 16);
        }
#pragma unroll
        for (int nt = 0; nt < 4; nt++)
            bh[nt] = *(const uint2*)(st + 8192 + (wn + nt) * 256 + lane * 8);

        if (kc + 3 < NKT) issue(kc + 3);

#pragma unroll
        for (int mt = 0; mt < 4; mt++)
#pragma unroll
            for (int nt = 0; nt < 4; nt++) mma16(acc[mt][nt], ah[mt], bh[nt]);
#pragma unroll
        for (int mt = 0; mt < 4; mt++)
#pragma unroll
            for (int nt = 0; nt < 4; nt++) mma16(acc[mt][nt], al[mt], bh[nt]);
    }

    // epilogue: d0:(r,c) d1:(r,c+1) d2:(r+8,c) d3:(r+8,c+1); r=lane/4, c=2*(lane%4)
    const int rbase = mb * 128 + (warp >> 2) * 64 + (lane >> 2);
    const int cbase = nb * 128 + (warp & 3) * 32 + (lane & 3) * 2;
#pragma unroll
    for (int mt = 0; mt < 4; mt++) {
#pragma unroll
        for (int nt = 0; nt < 4; nt++) {
            const int r = rbase + mt * 16;
            const int c = cbase + nt * 8;
            float4 d = acc[mt][nt];
            if (Ch) {
                if (c < relu_limit) {
                    d.x = fmaxf(d.x, 0.f); d.y = fmaxf(d.y, 0.f);
                    d.z = fmaxf(d.z, 0.f); d.w = fmaxf(d.w, 0.f);
                }
                *(__half2*)(Ch + (size_t)r * N + c) =
                    __float22half2_rn(make_float2(d.x, d.y));
                *(__half2*)(Ch + (size_t)(r + 8) * N + c) =
                    __float22half2_rn(make_float2(d.z, d.w));
            } else {
                if (bias) {
                    float2 bb = *(const float2*)(bias + c);
                    d.x += bb.x; d.y += bb.y; d.z += bb.x; d.w += bb.y;
                }
                *(float2*)(C + (size_t)r * N + c)       = make_float2(d.x, d.y);
                *(float2*)(C + (size_t)(r + 8) * N + c) = make_float2(d.z, d.w);
            }
        }
    }
}

// ---------------------------------------------------------------------------
// KV partial: grid (96, 7); chunk c covers s in [c*448, c*448+448).
// k,v read as fp16, accumulated in fp32.
// ---------------------------------------------------------------------------
__global__ __launch_bounds__(256) void kv_part()
{
    const int bh = blockIdx.x;
    const int pc = blockIdx.y;
    const int b  = bh / 12;
    const int h  = bh % 12;

    __shared__ float Ks[64][64];
    __shared__ float Vs[64][64];

    const int tid = threadIdx.x;
    const int er  = tid >> 4;
    const int dg  = tid & 15;
    const int sl  = tid >> 2;    // 0..63 loader row
    const int ch  = tid & 3;     // 0..3, 16 halves each

    float4 acc0 = {0,0,0,0}, acc1 = {0,0,0,0}, acc2 = {0,0,0,0}, acc3 = {0,0,0,0};
    float4 ksum = {0,0,0,0};

    const size_t base_k = (size_t)(b * 3136) * 2304 + 768  + h * 64;
    const size_t base_v = (size_t)(b * 3136) * 2304 + 1536 + h * 64;
    const int s_lo = pc * 448, s_hi = s_lo + 448;

    for (int s0 = s_lo; s0 < s_hi; s0 += 64) {
        const __half* kp = g_qkv + base_k + (size_t)(s0 + sl) * 2304 + ch * 16;
        const __half* vp = g_qkv + base_v + (size_t)(s0 + sl) * 2304 + ch * 16;
#pragma unroll
        for (int c = 0; c < 2; c++) {
            uint4 kr = *(const uint4*)(kp + c * 8);
            uint4 vr = *(const uint4*)(vp + c * 8);
            float2 f;
            f = __half22float2(*(__half2*)&kr.x); Ks[sl][ch*16 + c*8 + 0] = f.x; Ks[sl][ch*16 + c*8 + 1] = f.y;
            f = __half22float2(*(__half2*)&kr.y); Ks[sl][ch*16 + c*8 + 2] = f.x; Ks[sl][ch*16 + c*8 + 3] = f.y;
            f = __half22float2(*(__half2*)&kr.z); Ks[sl][ch*16 + c*8 + 4] = f.x; Ks[sl][ch*16 + c*8 + 5] = f.y;
            f = __half22float2(*(__half2*)&kr.w); Ks[sl][ch*16 + c*8 + 6] = f.x; Ks[sl][ch*16 + c*8 + 7] = f.y;
            f = __half22float2(*(__half2*)&vr.x); Vs[sl][ch*16 + c*8 + 0] = f.x; Vs[sl][ch*16 + c*8 + 1] = f.y;
            f = __half22float2(*(__half2*)&vr.y); Vs[sl][ch*16 + c*8 + 2] = f.x; Vs[sl][ch*16 + c*8 + 3] = f.y;
            f = __half22float2(*(__half2*)&vr.z); Vs[sl][ch*16 + c*8 + 4] = f.x; Vs[sl][ch*16 + c*8 + 5] = f.y;
            f = __half22float2(*(__half2*)&vr.w); Vs[sl][ch*16 + c*8 + 6] = f.x; Vs[sl][ch*16 + c*8 + 7] = f.y;
        }
        __syncthreads();

#pragma unroll 8
        for (int s = 0; s < 64; s++) {
            float4 k4 = *(const float4*)&Ks[s][er * 4];
            float4 v4 = *(const float4*)&Vs[s][dg * 4];
            acc0.x += k4.x * v4.x; acc0.y += k4.x * v4.y; acc0.z += k4.x * v4.z; acc0.w += k4.x * v4.w;
            acc1.x += k4.y * v4.x; acc1.y += k4.y * v4.y; acc1.z += k4.y * v4.z; acc1.w += k4.y * v4.w;
            acc2.x += k4.z * v4.x; acc2.y += k4.z * v4.y; acc2.z += k4.z * v4.z; acc2.w += k4.z * v4.w;
            acc3.x += k4.w * v4.x; acc3.y += k4.w * v4.y; acc3.z += k4.w * v4.z; acc3.w += k4.w * v4.w;
            if (dg == 0) {
                ksum.x += k4.x; ksum.y += k4.y; ksum.z += k4.z; ksum.w += k4.w;
            }
        }
        __syncthreads();
    }

    float* kvp = g_kvp + (size_t)(pc * 96 + bh) * 4096;
    *(float4*)&kvp[(er * 4 + 0) * 64 + dg * 4] = acc0;
    *(float4*)&kvp[(er * 4 + 1) * 64 + dg * 4] = acc1;
    *(float4*)&kvp[(er * 4 + 2) * 64 + dg * 4] = acc2;
    *(float4*)&kvp[(er * 4 + 3) * 64 + dg * 4] = acc3;
    if (dg == 0) *(float4*)&g_ksump[(pc * 96 + bh) * 64 + er * 4] = ksum;
}

// ---------------------------------------------------------------------------
// Reduce 7 partials (fixed order) + emit kv as fp16 hi/lo B-fragments.
// ---------------------------------------------------------------------------
__global__ __launch_bounds__(256) void kv_reduce()
{
    const int bh = blockIdx.x;
    const int tid = threadIdx.x;
    __shared__ float kvb[4096];
    __shared__ float kss[64];

#pragma unroll 1
    for (int i = tid * 4; i < 4096; i += 1024) {
        float4 s = make_float4(0.f, 0.f, 0.f, 0.f);
#pragma unroll
        for (int p = 0; p < 7; p++) {
            float4 v = *(const float4*)&g_kvp[(size_t)(p * 96 + bh) * 4096 + i];
            s.x += v.x; s.y += v.y; s.z += v.z; s.w += v.w;
        }
        *(float4*)&kvb[i] = s;
    }
    if (tid < 64) {
        float s = 0.f;
#pragma unroll
        for (int p = 0; p < 7; p++) s += g_ksump[(p * 96 + bh) * 64 + tid];
        kss[tid] = s;
        g_ksum[bh * 64 + tid] = s;
    }
    __syncthreads();

    // B-frag layout: [part(2)][kc(4)][nt(8)][lane(32)] uint2
    // b0 = {kv[e0][n], kv[e0+1][n]}, b1 = {kv[e0+8][n], kv[e0+9][n]}
    char* dst = (char*)g_kvfrag + (size_t)bh * 16384;
#pragma unroll
    for (int pos = tid; pos < 1024; pos += 256) {
        const int kc = pos >> 8, nt = (pos >> 5) & 7, ln = pos & 31;
        const int e0 = kc * 16 + 2 * (ln & 3);
        const int n  = nt * 8 + (ln >> 2);
        float v0 = kvb[e0 * 64 + n],       v1 = kvb[(e0 + 1) * 64 + n];
        float v2 = kvb[(e0 + 8) * 64 + n], v3 = kvb[(e0 + 9) * 64 + n];
        uint32_t l0, l1;
        uint32_t h0 = split2h(make_float2(v0, v1), l0);
        uint32_t h1 = split2h(make_float2(v2, v3), l1);
        *(uint2*)(dst + pos * 8)        = make_uint2(h0, h1);
        *(uint2*)(dst + 8192 + pos * 8) = make_uint2(l0, l1);
    }
}

// ---------------------------------------------------------------------------
// vo_gemm: per (bh, 64-token tile): out = (q @ kv) * z, z = 1/(q.ksum+eps),
// written directly as fp16 hi/lo fragments into g_a2s.
// 128 threads = 4 warps, warp = one m16 tile. kv as 2-term hi/lo B-frags.
// ---------------------------------------------------------------------------
__global__ __launch_bounds__(128) void vo_gemm()
{
    const int bh   = blockIdx.x;
    const int tile = blockIdx.y;      // 0..48
    const int b = bh / 12, h = bh % 12;

    __shared__ char bfr[16384];
    __shared__ float ks[64];

    const int tid = threadIdx.x, lane = tid & 31, warp = tid >> 5;
    const uint32_t sb = smem_u32(bfr);

    // load kv frags (16KB) via cp.async + ksum
    const char* src = (const char*)g_kvfrag + (size_t)bh * 16384;
#pragma unroll
    for (int i = 0; i < 8; i++) {
        const int c = tid + i * 128;
        asm volatile("cp.async.ca.shared.global [%0], [%1], 16;"
                     :: "r"(sb + c * 16), "l"(src + c * 16));
    }
    asm volatile("cp.async.commit_group;");
    if (tid < 64) ks[tid] = g_ksum[bh * 64 + tid];
    asm volatile("cp.async.wait_group 0;" ::: "memory");
    __syncthreads();

    const int r  = lane >> 2;
    const int c2 = 2 * (lane & 3);
    const size_t tok0 = (size_t)b * 3136 + tile * 64 + warp * 16;
    const __half* qbase = g_qkv + tok0 * 2304 + h * 64;

    // q A-fragments + z dot accumulation
    uint32_t a[4][4];
    float dr = 0.f, dr8 = 0.f;
#pragma unroll
    for (int kc = 0; kc < 4; kc++) {
        const int e0 = kc * 16 + c2;
        a[kc][0] = *(const uint32_t*)(qbase + (size_t)r * 2304 + e0);
        a[kc][1] = *(const uint32_t*)(qbase + (size_t)(r + 8) * 2304 + e0);
        a[kc][2] = *(const uint32_t*)(qbase + (size_t)r * 2304 + e0 + 8);
        a[kc][3] = *(const uint32_t*)(qbase + (size_t)(r + 8) * 2304 + e0 + 8);
        float2 f0 = __half22float2(*(__half2*)&a[kc][0]);
        float2 f1 = __half22float2(*(__half2*)&a[kc][1]);
        float2 f2 = __half22float2(*(__half2*)&a[kc][2]);
        float2 f3 = __half22float2(*(__half2*)&a[kc][3]);
        dr  += f0.x * ks[e0] + f0.y * ks[e0 + 1] + f2.x * ks[e0 + 8] + f2.y * ks[e0 + 9];
        dr8 += f1.x * ks[e0] + f1.y * ks[e0 + 1] + f3.x * ks[e0 + 8] + f3.y * ks[e0 + 9];
    }
    dr  += __shfl_xor_sync(FULL_MASK, dr, 1);  dr  += __shfl_xor_sync(FULL_MASK, dr, 2);
    dr8 += __shfl_xor_sync(FULL_MASK, dr8, 1); dr8 += __shfl_xor_sync(FULL_MASK, dr8, 2);
    const float zr  = 1.0f / (dr + 1e-4f);
    const float zr8 = 1.0f / (dr8 + 1e-4f);

    float4 acc[8];
#pragma unroll
    for (int nt = 0; nt < 8; nt++) acc[nt] = make_float4(0.f, 0.f, 0.f, 0.f);

#pragma unroll
    for (int part = 0; part < 2; part++) {
#pragma unroll
        for (int kc = 0; kc < 4; kc++) {
            const char* pb = bfr + part * 8192 + kc * 2048;
            uint4 av = make_uint4(a[kc][0], a[kc][1], a[kc][2], a[kc][3]);
#pragma unroll
            for (int nt = 0; nt < 8; nt++) {
                uint2 bb = *(const uint2*)(pb + nt * 256 + lane * 8);
                mma16(acc[nt], av, bb);
            }
        }
    }

    // epilogue: write g_a2s fragments.
    // out col n2 = nt*8 + 2*(lane&3); kt = h*4 + (nt>>1); L = lane; r_reg low=2*(nt&1)
    const int mb = (int)(tok0 >> 7);
    const int mt = ((int)tok0 >> 4) & 7;
    char* abase = (char*)g_a2s;
#pragma unroll
    for (int nt = 0; nt < 8; nt++) {
        const int kt = h * 4 + (nt >> 1);
        char* p = abase + (((size_t)(mb * 48 + kt)) << 13) + mt * 512 + lane * 16 + (nt & 1) * 8;
        uint32_t lo;
        uint32_t hi = split2h(make_float2(acc[nt].x * zr, acc[nt].y * zr), lo);
        *(uint32_t*)p          = hi;
        *(uint32_t*)(p + 4096) = lo;
        hi = split2h(make_float2(acc[nt].z * zr8, acc[nt].w * zr8), lo);
        *(uint32_t*)(p + 4)        = hi;
        *(uint32_t*)(p + 4096 + 4) = lo;
    }
}

// ---------------------------------------------------------------------------
extern "C" void kernel_launch(void* const* d_in, const int* in_sizes, int n_in,
                              void* d_out, int out_size)
{
    const float* x     = (const float*)d_in[0];
    const float* Wqkv  = (const float*)d_in[1];
    const float* Wproj = (const float*)d_in[2];
    const float* bproj = (const float*)d_in[3];
    float* out = (float*)d_out;

    __half* qkv_p;
    uint4 *a1s, *a2s, *b1s, *b2s;
    cudaGetSymbolAddress((void**)&qkv_p, g_qkv);
    cudaGetSymbolAddress((void**)&a1s, g_a1s);
    cudaGetSymbolAddress((void**)&a2s, g_a2s);
    cudaGetSymbolAddress((void**)&b1s, g_b1s);
    cudaGetSymbolAddress((void**)&b2s, g_b2s);

    // 0) pre-split weights + input into fp16 fragment tiles
    split_b<<<2304 / 8, 256>>>(Wqkv,  b1s, 768);
    split_b<<<768 / 8, 256>>>(Wproj, b2s, 768);
    split_a<<<M_TOK / 16, 256>>>(x, a1s, 768);

    // 1) qkv = x @ Wqkv^T -> fp16 (fused ReLU on q,k cols < 1536)
    gemm_f16<<<dim3(2304 / 128, M_TOK / 128), 256>>>(
        a1s, b1s, nullptr, qkv_p, M_TOK, 2304, 768, nullptr, 1536);

    // 2) kv and k_sum per (b,h): S-split partials + reduce (+ kv frag emit)
    kv_part<<<dim3(96, 7), 256>>>();
    kv_reduce<<<96, 256>>>();

    // 3) out = (q @ kv) * z as tensor-core GEMM -> fp16 fragments (GEMM2's A)
    vo_gemm<<<dim3(96, 49), 128>>>();

    // 4) out = attn @ Wproj^T + bproj (fp32 out)
    gemm_f16<<<dim3(768 / 128, M_TOK / 128), 256>>>(
        a2s, b2s, out, nullptr, M_TOK, 768, 768, bproj, 0);
}

// round 11
// speedup vs baseline: 1.8891x; 1.2243x over previous
#include <cuda_runtime.h>
#include <cuda_fp16.h>
#include <cstdint>
#include <cstddef>

#define FULL_MASK 0xFFFFFFFFu

// Problem constants: B=128, N=196, C=768, h=12, e=64, frames=16
// tokens M = 25088 ; b = 8 ; S = 3136 ; bh = 96
static const int M_TOK = 25088;

// ---------------------------------------------------------------------------
// Scratch (allocation-free: __device__ globals)
// ---------------------------------------------------------------------------
__device__ __half g_qkv[(size_t)25088 * 2304]; // [tok][3*C] (q|k|v) fp16, q/k ReLU'd
__device__ float g_ksum[96 * 64];               // [bh][e]
__device__ float g_kvp[7 * 96 * 64 * 64];       // S-split partials
__device__ float g_ksump[7 * 96 * 64];
__device__ uint2 g_kvfrag[96 * 2048];           // [bh][part(2)][kc(4)][nt(8)][lane(32)] uint2

// fp16 fragment-ordered tiles.
// A1 (x, hi only):  [mb][kt][mtile(8)][512B]          -> chunk 4KB
// A2 (attn, hi+lo): [mb][kt][part(2)][mtile(8)][512B] -> chunk 8KB
// B  (hi only):     [nb][kt][ntile(16)][256B]         -> chunk 4KB
__device__ uint4 g_a1s[(25088 / 16) * (768 / 16) * 32];   // 38.5 MB (x, hi)
__device__ uint4 g_a2s[(25088 / 16) * (768 / 16) * 64];   // 77.1 MB (attn hi+lo)
__device__ uint4 g_b1s[(2304 / 8) * (768 / 16) * 16];     // 3.5 MB (Wqkv)
__device__ uint4 g_b2s[(768 / 8) * (768 / 16) * 16];      // 1.2 MB (Wproj)

// ---------------------------------------------------------------------------
__device__ __forceinline__ uint32_t smem_u32(const void* p) {
    uint32_t r;
    asm("{.reg .u64 t; cvta.to.shared.u64 t, %1; cvt.u32.u64 %0, t;}" : "=r"(r) : "l"(p));
    return r;
}

// Split float2 -> hi f16x2 (return) + residual f16x2 (lo). low half = .x
__device__ __forceinline__ uint32_t split2h(float2 v, uint32_t& lo) {
    __half2 h = __float22half2_rn(v);
    float2 back = __half22float2(h);
    __half2 l = __float22half2_rn(make_float2(v.x - back.x, v.y - back.y));
    lo = *(uint32_t*)&l;
    return *(uint32_t*)&h;
}
__device__ __forceinline__ uint32_t cvt2h(float2 v) {
    __half2 h = __float22half2_rn(v);
    return *(uint32_t*)&h;
}

// mma.sync m16n8k16 fp16: d += a*b (row.col, f32 accum)
__device__ __forceinline__ void mma16(float4& d, uint4 a, uint2 b) {
    asm volatile(
        "mma.sync.aligned.m16n8k16.row.col.f32.f16.f16.f32 "
        "{%0,%1,%2,%3}, {%4,%5,%6,%7}, {%8,%9}, {%0,%1,%2,%3};"
        : "+f"(d.x), "+f"(d.y), "+f"(d.z), "+f"(d.w)
        : "r"(a.x), "r"(a.y), "r"(a.z), "r"(a.w), "r"(b.x), "r"(b.y));
}

// ---------------------------------------------------------------------------
// split_a: fp32 [M][K] -> A-frag tiles (hi fp16 only), m16n8k16 A layout.
// ---------------------------------------------------------------------------
__global__ __launch_bounds__(256) void split_a(const float* __restrict__ src,
                                               uint4* __restrict__ dst, int K)
{
    const int NKT  = K >> 4;
    const int strip = blockIdx.x;
    const int warp = threadIdx.x >> 5, lane = threadIdx.x & 31;
    const int mb = strip >> 3, mt = strip & 7;
    const int c2 = (lane & 3) * 2;
    const float* row0 = src + (size_t)(strip * 16 + (lane >> 2)) * K;
    const float* row1 = row0 + (size_t)8 * K;
    char* base = (char*)dst;

    for (int kt = warp; kt < NKT; kt += 8) {
        const int kb = kt * 16;
        uint32_t h0 = cvt2h(*(const float2*)(row0 + kb + c2));
        uint32_t h1 = cvt2h(*(const float2*)(row1 + kb + c2));
        uint32_t h2 = cvt2h(*(const float2*)(row0 + kb + c2 + 8));
        uint32_t h3 = cvt2h(*(const float2*)(row1 + kb + c2 + 8));
        size_t off = ((size_t)(mb * NKT + kt) << 12) + mt * 512 + lane * 16;
        *(uint4*)(base + off) = make_uint4(h0, h1, h2, h3);
    }
}

// ---------------------------------------------------------------------------
// split_b: fp32 [N][K] -> B-frag tiles (hi fp16 only), m16n8k16 B layout.
// ---------------------------------------------------------------------------
__global__ __launch_bounds__(256) void split_b(const float* __restrict__ src,
                                               uint4* __restrict__ dst, int K)
{
    const int NKT  = K >> 4;
    const int strip = blockIdx.x;
    const int warp = threadIdx.x >> 5, lane = threadIdx.x & 31;
    const int nb = strip >> 4, nt = strip & 15;
    const int c2 = (lane & 3) * 2;
    const float* row = src + (size_t)(strip * 8 + (lane >> 2)) * K;
    char* base = (char*)dst;

    for (int kt = warp; kt < NKT; kt += 8) {
        const int kb = kt * 16;
        uint32_t h0 = cvt2h(*(const float2*)(row + kb + c2));
        uint32_t h1 = cvt2h(*(const float2*)(row + kb + c2 + 8));
        size_t off = ((size_t)(nb * NKT + kt) << 12) + nt * 256 + lane * 8;
        *(uint2*)(base + off) = make_uint2(h0, h1);
    }
}

// ---------------------------------------------------------------------------
// fp16 HMMA GEMM on pre-split tiles. USE_LO: A has hi+lo parts (2-term).
// 256 threads, 128x128 tile, BK=16, 4-stage cp.async ring, 2 CTAs/SM.
// Output: half (Ch, ReLU<relu_limit) or fp32 (C, +bias).
// ---------------------------------------------------------------------------
template <bool USE_LO>
__global__ __launch_bounds__(256, 2) void gemm_f16(
    const uint4* __restrict__ As, const uint4* __restrict__ Bs,
    float* __restrict__ C, __half* __restrict__ Ch,
    int M, int N, int K, const float* __restrict__ bias, int relu_limit)
{
    constexpr int ACH = USE_LO ? 8192 : 4096;   // A chunk bytes in gmem
    constexpr int STG = USE_LO ? 12288 : 8192;  // stage bytes in smem
    constexpr int BOFF = USE_LO ? 8192 : 4096;  // B offset within stage

    __shared__ char smem[4 * STG];

    const int tid  = threadIdx.x;
    const int lane = tid & 31;
    const int warp = tid >> 5;
    const int mb   = blockIdx.y;
    const int nb   = blockIdx.x;
    const int NKT  = K >> 4;
    const uint32_t sb = smem_u32(smem);

    const char* Abase = (const char*)As + (size_t)mb * NKT * ACH;
    const char* Bbase = (const char*)Bs + ((size_t)nb * NKT << 12);

    auto issue = [&](int kc) {
        const char* asrc = Abase + (size_t)kc * ACH;
        const char* bsrc = Bbase + ((size_t)kc << 12);
        const uint32_t dst0 = sb + (kc & 3) * STG;
#pragma unroll
        for (int i = 0; i < (USE_LO ? 2 : 1); i++) {
            const int c = tid + i * 256;
            asm volatile("cp.async.ca.shared.global [%0], [%1], 16;"
                         :: "r"(dst0 + c * 16), "l"(asrc + c * 16));
        }
        asm volatile("cp.async.ca.shared.global [%0], [%1], 16;"
                     :: "r"(dst0 + BOFF + tid * 16), "l"(bsrc + tid * 16));
        asm volatile("cp.async.commit_group;");
    };

    float4 acc[4][4];
#pragma unroll
    for (int i = 0; i < 4; i++)
#pragma unroll
        for (int j = 0; j < 4; j++) acc[i][j] = make_float4(0.f, 0.f, 0.f, 0.f);

    const int wm = (warp >> 2) * 4;   // A m-tile base (of 8)
    const int wn = (warp & 3) * 4;    // B n-tile base (of 16)

    issue(0); issue(1); issue(2);

#pragma unroll 1
    for (int kc = 0; kc < NKT; kc++) {
        const int remain = NKT - 1 - kc;
        if (remain >= 2)      asm volatile("cp.async.wait_group 2;" ::: "memory");
        else if (remain == 1) asm volatile("cp.async.wait_group 1;" ::: "memory");
        else                  asm volatile("cp.async.wait_group 0;" ::: "memory");
        __syncthreads();

        const char* st = smem + (kc & 3) * STG;

        uint4 ah[4], al[4];
        uint2 bh[4];
#pragma unroll
        for (int mt = 0; mt < 4; mt++) {
            ah[mt] = *(const uint4*)(st + (wm + mt) * 512 + lane * 16);
            if (USE_LO)
                al[mt] = *(const uint4*)(st + 4096 + (wm + mt) * 512 + lane * 16);
        }
#pragma unroll
        for (int nt = 0; nt < 4; nt++)
            bh[nt] = *(const uint2*)(st + BOFF + (wn + nt) * 256 + lane * 8);

        if (kc + 3 < NKT) issue(kc + 3);

#pragma unroll
        for (int mt = 0; mt < 4; mt++)
#pragma unroll
            for (int nt = 0; nt < 4; nt++) mma16(acc[mt][nt], ah[mt], bh[nt]);
        if (USE_LO) {
#pragma unroll
            for (int mt = 0; mt < 4; mt++)
#pragma unroll
                for (int nt = 0; nt < 4; nt++) mma16(acc[mt][nt], al[mt], bh[nt]);
        }
    }

    // epilogue: d0:(r,c) d1:(r,c+1) d2:(r+8,c) d3:(r+8,c+1); r=lane/4, c=2*(lane%4)
    const int rbase = mb * 128 + (warp >> 2) * 64 + (lane >> 2);
    const int cbase = nb * 128 + (warp & 3) * 32 + (lane & 3) * 2;
#pragma unroll
    for (int mt = 0; mt < 4; mt++) {
#pragma unroll
        for (int nt = 0; nt < 4; nt++) {
            const int r = rbase + mt * 16;
            const int c = cbase + nt * 8;
            float4 d = acc[mt][nt];
            if (Ch) {
                if (c < relu_limit) {
                    d.x = fmaxf(d.x, 0.f); d.y = fmaxf(d.y, 0.f);
                    d.z = fmaxf(d.z, 0.f); d.w = fmaxf(d.w, 0.f);
                }
                *(__half2*)(Ch + (size_t)r * N + c) =
                    __float22half2_rn(make_float2(d.x, d.y));
                *(__half2*)(Ch + (size_t)(r + 8) * N + c) =
                    __float22half2_rn(make_float2(d.z, d.w));
            } else {
                if (bias) {
                    float2 bb = *(const float2*)(bias + c);
                    d.x += bb.x; d.y += bb.y; d.z += bb.x; d.w += bb.y;
                }
                *(float2*)(C + (size_t)r * N + c)       = make_float2(d.x, d.y);
                *(float2*)(C + (size_t)(r + 8) * N + c) = make_float2(d.z, d.w);
            }
        }
    }
}

// ---------------------------------------------------------------------------
// KV partial: grid (96, 7); chunk c covers s in [c*448, c*448+448).
// k,v read as fp16, accumulated in fp32.
// ---------------------------------------------------------------------------
__global__ __launch_bounds__(256) void kv_part()
{
    const int bh = blockIdx.x;
    const int pc = blockIdx.y;
    const int b  = bh / 12;
    const int h  = bh % 12;

    __shared__ float Ks[64][64];
    __shared__ float Vs[64][64];

    const int tid = threadIdx.x;
    const int er  = tid >> 4;
    const int dg  = tid & 15;
    const int sl  = tid >> 2;
    const int ch  = tid & 3;

    float4 acc0 = {0,0,0,0}, acc1 = {0,0,0,0}, acc2 = {0,0,0,0}, acc3 = {0,0,0,0};
    float4 ksum = {0,0,0,0};

    const size_t base_k = (size_t)(b * 3136) * 2304 + 768  + h * 64;
    const size_t base_v = (size_t)(b * 3136) * 2304 + 1536 + h * 64;
    const int s_lo = pc * 448, s_hi = s_lo + 448;

    for (int s0 = s_lo; s0 < s_hi; s0 += 64) {
        const __half* kp = g_qkv + base_k + (size_t)(s0 + sl) * 2304 + ch * 16;
        const __half* vp = g_qkv + base_v + (size_t)(s0 + sl) * 2304 + ch * 16;
#pragma unroll
        for (int c = 0; c < 2; c++) {
            uint4 kr = *(const uint4*)(kp + c * 8);
            uint4 vr = *(const uint4*)(vp + c * 8);
            float2 f;
            f = __half22float2(*(__half2*)&kr.x); Ks[sl][ch*16 + c*8 + 0] = f.x; Ks[sl][ch*16 + c*8 + 1] = f.y;
            f = __half22float2(*(__half2*)&kr.y); Ks[sl][ch*16 + c*8 + 2] = f.x; Ks[sl][ch*16 + c*8 + 3] = f.y;
            f = __half22float2(*(__half2*)&kr.z); Ks[sl][ch*16 + c*8 + 4] = f.x; Ks[sl][ch*16 + c*8 + 5] = f.y;
            f = __half22float2(*(__half2*)&kr.w); Ks[sl][ch*16 + c*8 + 6] = f.x; Ks[sl][ch*16 + c*8 + 7] = f.y;
            f = __half22float2(*(__half2*)&vr.x); Vs[sl][ch*16 + c*8 + 0] = f.x; Vs[sl][ch*16 + c*8 + 1] = f.y;
            f = __half22float2(*(__half2*)&vr.y); Vs[sl][ch*16 + c*8 + 2] = f.x; Vs[sl][ch*16 + c*8 + 3] = f.y;
            f = __half22float2(*(__half2*)&vr.z); Vs[sl][ch*16 + c*8 + 4] = f.x; Vs[sl][ch*16 + c*8 + 5] = f.y;
            f = __half22float2(*(__half2*)&vr.w); Vs[sl][ch*16 + c*8 + 6] = f.x; Vs[sl][ch*16 + c*8 + 7] = f.y;
        }
        __syncthreads();

#pragma unroll 8
        for (int s = 0; s < 64; s++) {
            float4 k4 = *(const float4*)&Ks[s][er * 4];
            float4 v4 = *(const float4*)&Vs[s][dg * 4];
            acc0.x += k4.x * v4.x; acc0.y += k4.x * v4.y; acc0.z += k4.x * v4.z; acc0.w += k4.x * v4.w;
            acc1.x += k4.y * v4.x; acc1.y += k4.y * v4.y; acc1.z += k4.y * v4.z; acc1.w += k4.y * v4.w;
            acc2.x += k4.z * v4.x; acc2.y += k4.z * v4.y; acc2.z += k4.z * v4.z; acc2.w += k4.z * v4.w;
            acc3.x += k4.w * v4.x; acc3.y += k4.w * v4.y; acc3.z += k4.w * v4.z; acc3.w += k4.w * v4.w;
            if (dg == 0) {
                ksum.x += k4.x; ksum.y += k4.y; ksum.z += k4.z; ksum.w += k4.w;
            }
        }
        __syncthreads();
    }

    float* kvp = g_kvp + (size_t)(pc * 96 + bh) * 4096;
    *(float4*)&kvp[(er * 4 + 0) * 64 + dg * 4] = acc0;
    *(float4*)&kvp[(er * 4 + 1) * 64 + dg * 4] = acc1;
    *(float4*)&kvp[(er * 4 + 2) * 64 + dg * 4] = acc2;
    *(float4*)&kvp[(er * 4 + 3) * 64 + dg * 4] = acc3;
    if (dg == 0) *(float4*)&g_ksump[(pc * 96 + bh) * 64 + er * 4] = ksum;
}

// ---------------------------------------------------------------------------
// Reduce 7 partials (fixed order) + emit kv as fp16 hi/lo B-fragments.
// ---------------------------------------------------------------------------
__global__ __launch_bounds__(256) void kv_reduce()
{
    const int bh = blockIdx.x;
    const int tid = threadIdx.x;
    __shared__ float kvb[4096];

#pragma unroll 1
    for (int i = tid * 4; i < 4096; i += 1024) {
        float4 s = make_float4(0.f, 0.f, 0.f, 0.f);
#pragma unroll
        for (int p = 0; p < 7; p++) {
            float4 v = *(const float4*)&g_kvp[(size_t)(p * 96 + bh) * 4096 + i];
            s.x += v.x; s.y += v.y; s.z += v.z; s.w += v.w;
        }
        *(float4*)&kvb[i] = s;
    }
    if (tid < 64) {
        float s = 0.f;
#pragma unroll
        for (int p = 0; p < 7; p++) s += g_ksump[(p * 96 + bh) * 64 + tid];
        g_ksum[bh * 64 + tid] = s;
    }
    __syncthreads();

    // B-frag layout: [part(2)][kc(4)][nt(8)][lane(32)] uint2
    char* dst = (char*)g_kvfrag + (size_t)bh * 16384;
#pragma unroll
    for (int pos = tid; pos < 1024; pos += 256) {
        const int kc = pos >> 8, nt = (pos >> 5) & 7, ln = pos & 31;
        const int e0 = kc * 16 + 2 * (ln & 3);
        const int n  = nt * 8 + (ln >> 2);
        float v0 = kvb[e0 * 64 + n],       v1 = kvb[(e0 + 1) * 64 + n];
        float v2 = kvb[(e0 + 8) * 64 + n], v3 = kvb[(e0 + 9) * 64 + n];
        uint32_t l0, l1;
        uint32_t h0 = split2h(make_float2(v0, v1), l0);
        uint32_t h1 = split2h(make_float2(v2, v3), l1);
        *(uint2*)(dst + pos * 8)        = make_uint2(h0, h1);
        *(uint2*)(dst + 8192 + pos * 8) = make_uint2(l0, l1);
    }
}

// ---------------------------------------------------------------------------
// vo_gemm: per (bh, 64-token tile): out = (q @ kv) * z, z = 1/(q.ksum+eps),
// written directly as fp16 hi/lo fragments into g_a2s.
// ---------------------------------------------------------------------------
__global__ __launch_bounds__(128) void vo_gemm()
{
    const int bh   = blockIdx.x;
    const int tile = blockIdx.y;      // 0..48
    const int b = bh / 12, h = bh % 12;

    __shared__ char bfr[16384];
    __shared__ float ks[64];

    const int tid = threadIdx.x, lane = tid & 31, warp = tid >> 5;
    const uint32_t sb = smem_u32(bfr);

    const char* src = (const char*)g_kvfrag + (size_t)bh * 16384;
#pragma unroll
    for (int i = 0; i < 8; i++) {
        const int c = tid + i * 128;
        asm volatile("cp.async.ca.shared.global [%0], [%1], 16;"
                     :: "r"(sb + c * 16), "l"(src + c * 16));
    }
    asm volatile("cp.async.commit_group;");
    if (tid < 64) ks[tid] = g_ksum[bh * 64 + tid];
    asm volatile("cp.async.wait_group 0;" ::: "memory");
    __syncthreads();

    const int r  = lane >> 2;
    const int c2 = 2 * (lane & 3);
    const size_t tok0 = (size_t)b * 3136 + tile * 64 + warp * 16;
    const __half* qbase = g_qkv + tok0 * 2304 + h * 64;

    uint32_t a[4][4];
    float dr = 0.f, dr8 = 0.f;
#pragma unroll
    for (int kc = 0; kc < 4; kc++) {
        const int e0 = kc * 16 + c2;
        a[kc][0] = *(const uint32_t*)(qbase + (size_t)r * 2304 + e0);
        a[kc][1] = *(const uint32_t*)(qbase + (size_t)(r + 8) * 2304 + e0);
        a[kc][2] = *(const uint32_t*)(qbase + (size_t)r * 2304 + e0 + 8);
        a[kc][3] = *(const uint32_t*)(qbase + (size_t)(r + 8) * 2304 + e0 + 8);
        float2 f0 = __half22float2(*(__half2*)&a[kc][0]);
        float2 f1 = __half22float2(*(__half2*)&a[kc][1]);
        float2 f2 = __half22float2(*(__half2*)&a[kc][2]);
        float2 f3 = __half22float2(*(__half2*)&a[kc][3]);
        dr  += f0.x * ks[e0] + f0.y * ks[e0 + 1] + f2.x * ks[e0 + 8] + f2.y * ks[e0 + 9];
        dr8 += f1.x * ks[e0] + f1.y * ks[e0 + 1] + f3.x * ks[e0 + 8] + f3.y * ks[e0 + 9];
    }
    dr  += __shfl_xor_sync(FULL_MASK, dr, 1);  dr  += __shfl_xor_sync(FULL_MASK, dr, 2);
    dr8 += __shfl_xor_sync(FULL_MASK, dr8, 1); dr8 += __shfl_xor_sync(FULL_MASK, dr8, 2);
    const float zr  = 1.0f / (dr + 1e-4f);
    const float zr8 = 1.0f / (dr8 + 1e-4f);

    float4 acc[8];
#pragma unroll
    for (int nt = 0; nt < 8; nt++) acc[nt] = make_float4(0.f, 0.f, 0.f, 0.f);

#pragma unroll
    for (int part = 0; part < 2; part++) {
#pragma unroll
        for (int kc = 0; kc < 4; kc++) {
            const char* pb = bfr + part * 8192 + kc * 2048;
            uint4 av = make_uint4(a[kc][0], a[kc][1], a[kc][2], a[kc][3]);
#pragma unroll
            for (int nt = 0; nt < 8; nt++) {
                uint2 bb = *(const uint2*)(pb + nt * 256 + lane * 8);
                mma16(acc[nt], av, bb);
            }
        }
    }

    const int mb = (int)(tok0 >> 7);
    const int mt = ((int)tok0 >> 4) & 7;
    char* abase = (char*)g_a2s;
#pragma unroll
    for (int nt = 0; nt < 8; nt++) {
        const int kt = h * 4 + (nt >> 1);
        char* p = abase + (((size_t)(mb * 48 + kt)) << 13) + mt * 512 + lane * 16 + (nt & 1) * 8;
        uint32_t lo;
        uint32_t hi = split2h(make_float2(acc[nt].x * zr, acc[nt].y * zr), lo);
        *(uint32_t*)p          = hi;
        *(uint32_t*)(p + 4096) = lo;
        hi = split2h(make_float2(acc[nt].z * zr8, acc[nt].w * zr8), lo);
        *(uint32_t*)(p + 4)        = hi;
        *(uint32_t*)(p + 4096 + 4) = lo;
    }
}

// ---------------------------------------------------------------------------
extern "C" void kernel_launch(void* const* d_in, const int* in_sizes, int n_in,
                              void* d_out, int out_size)
{
    const float* x     = (const float*)d_in[0];
    const float* Wqkv  = (const float*)d_in[1];
    const float* Wproj = (const float*)d_in[2];
    const float* bproj = (const float*)d_in[3];
    float* out = (float*)d_out;

    __half* qkv_p;
    uint4 *a1s, *a2s, *b1s, *b2s;
    cudaGetSymbolAddress((void**)&qkv_p, g_qkv);
    cudaGetSymbolAddress((void**)&a1s, g_a1s);
    cudaGetSymbolAddress((void**)&a2s, g_a2s);
    cudaGetSymbolAddress((void**)&b1s, g_b1s);
    cudaGetSymbolAddress((void**)&b2s, g_b2s);

    // 0) pre-split weights + input into fp16 fragment tiles
    split_b<<<2304 / 8, 256>>>(Wqkv,  b1s, 768);
    split_b<<<768 / 8, 256>>>(Wproj, b2s, 768);
    split_a<<<M_TOK / 16, 256>>>(x, a1s, 768);

    // 1) qkv = x @ Wqkv^T -> fp16 (1-term A, fused ReLU on q,k cols < 1536)
    gemm_f16<false><<<dim3(2304 / 128, M_TOK / 128), 256>>>(
        a1s, b1s, nullptr, qkv_p, M_TOK, 2304, 768, nullptr, 1536);

    // 2) kv and k_sum per (b,h): S-split partials + reduce (+ kv frag emit)
    kv_part<<<dim3(96, 7), 256>>>();
    kv_reduce<<<96, 256>>>();

    // 3) out = (q @ kv) * z as tensor-core GEMM -> fp16 hi/lo fragments
    vo_gemm<<<dim3(96, 49), 128>>>();

    // 4) out = attn @ Wproj^T + bproj (2-term A, fp32 out)
    gemm_f16<true><<<dim3(768 / 128, M_TOK / 128), 256>>>(
        a2s, b2s, out, nullptr, M_TOK, 768, 768, bproj, 0);
}

// round 12
// speedup vs baseline: 1.9487x; 1.0315x over previous
#include <cuda_runtime.h>
#include <cuda_fp16.h>
#include <cstdint>
#include <cstddef>

#define FULL_MASK 0xFFFFFFFFu

// Problem constants: B=128, N=196, C=768, h=12, e=64, frames=16
// tokens M = 25088 ; b = 8 ; S = 3136 ; bh = 96
static const int M_TOK = 25088;

// ---------------------------------------------------------------------------
// Scratch (allocation-free: __device__ globals)
// ---------------------------------------------------------------------------
__device__ __half g_qkv[(size_t)25088 * 2304]; // [tok][3*C] (q|k|v) fp16, q/k ReLU'd
__device__ float g_ksum[96 * 64];               // [bh][e]
__device__ float g_kvp[7 * 96 * 64 * 64];       // S-split partials
__device__ float g_ksump[7 * 96 * 64];
__device__ uint2 g_kvfrag[96 * 2048];           // [bh][part(2)][kc(4)][nt(8)][lane(32)] uint2

// fp16 fragment-ordered tiles.
// A1 (x, hi only):  [mb][kt][mtile(8)][512B]          -> chunk 4KB
// A2 (attn, hi+lo): [mb][kt][part(2)][mtile(8)][512B] -> chunk 8KB
// B  (hi only):     [nb][kt][ntile(16)][256B]         -> chunk 4KB
__device__ uint4 g_a1s[(25088 / 16) * (768 / 16) * 32];   // 38.5 MB (x, hi)
__device__ uint4 g_a2s[(25088 / 16) * (768 / 16) * 64];   // 77.1 MB (attn hi+lo)
__device__ uint4 g_b1s[(2304 / 8) * (768 / 16) * 16];     // 3.5 MB (Wqkv)
__device__ uint4 g_b2s[(768 / 8) * (768 / 16) * 16];      // 1.2 MB (Wproj)

// ---------------------------------------------------------------------------
__device__ __forceinline__ uint32_t smem_u32(const void* p) {
    uint32_t r;
    asm("{.reg .u64 t; cvta.to.shared.u64 t, %1; cvt.u32.u64 %0, t;}" : "=r"(r) : "l"(p));
    return r;
}

// Split float2 -> hi f16x2 (return) + residual f16x2 (lo). low half = .x
__device__ __forceinline__ uint32_t split2h(float2 v, uint32_t& lo) {
    __half2 h = __float22half2_rn(v);
    float2 back = __half22float2(h);
    __half2 l = __float22half2_rn(make_float2(v.x - back.x, v.y - back.y));
    lo = *(uint32_t*)&l;
    return *(uint32_t*)&h;
}
__device__ __forceinline__ uint32_t cvt2h(float2 v) {
    __half2 h = __float22half2_rn(v);
    return *(uint32_t*)&h;
}

// mma.sync m16n8k16 fp16: d += a*b (row.col, f32 accum)
__device__ __forceinline__ void mma16(float4& d, uint4 a, uint2 b) {
    asm volatile(
        "mma.sync.aligned.m16n8k16.row.col.f32.f16.f16.f32 "
        "{%0,%1,%2,%3}, {%4,%5,%6,%7}, {%8,%9}, {%0,%1,%2,%3};"
        : "+f"(d.x), "+f"(d.y), "+f"(d.z), "+f"(d.w)
        : "r"(a.x), "r"(a.y), "r"(a.z), "r"(a.w), "r"(b.x), "r"(b.y));
}

// ---------------------------------------------------------------------------
// split_a: fp32 [M][K] -> A-frag tiles (hi fp16 only), m16n8k16 A layout.
// ---------------------------------------------------------------------------
__global__ __launch_bounds__(256) void split_a(const float* __restrict__ src,
                                               uint4* __restrict__ dst, int K)
{
    const int NKT  = K >> 4;
    const int strip = blockIdx.x;
    const int warp = threadIdx.x >> 5, lane = threadIdx.x & 31;
    const int mb = strip >> 3, mt = strip & 7;
    const int c2 = (lane & 3) * 2;
    const float* row0 = src + (size_t)(strip * 16 + (lane >> 2)) * K;
    const float* row1 = row0 + (size_t)8 * K;
    char* base = (char*)dst;

    for (int kt = warp; kt < NKT; kt += 8) {
        const int kb = kt * 16;
        uint32_t h0 = cvt2h(*(const float2*)(row0 + kb + c2));
        uint32_t h1 = cvt2h(*(const float2*)(row1 + kb + c2));
        uint32_t h2 = cvt2h(*(const float2*)(row0 + kb + c2 + 8));
        uint32_t h3 = cvt2h(*(const float2*)(row1 + kb + c2 + 8));
        size_t off = ((size_t)(mb * NKT + kt) << 12) + mt * 512 + lane * 16;
        *(uint4*)(base + off) = make_uint4(h0, h1, h2, h3);
    }
}

// ---------------------------------------------------------------------------
// split_b: fp32 [N][K] -> B-frag tiles (hi fp16 only), m16n8k16 B layout.
// ---------------------------------------------------------------------------
__global__ __launch_bounds__(256) void split_b(const float* __restrict__ src,
                                               uint4* __restrict__ dst, int K)
{
    const int NKT  = K >> 4;
    const int strip = blockIdx.x;
    const int warp = threadIdx.x >> 5, lane = threadIdx.x & 31;
    const int nb = strip >> 4, nt = strip & 15;
    const int c2 = (lane & 3) * 2;
    const float* row = src + (size_t)(strip * 8 + (lane >> 2)) * K;
    char* base = (char*)dst;

    for (int kt = warp; kt < NKT; kt += 8) {
        const int kb = kt * 16;
        uint32_t h0 = cvt2h(*(const float2*)(row + kb + c2));
        uint32_t h1 = cvt2h(*(const float2*)(row + kb + c2 + 8));
        size_t off = ((size_t)(nb * NKT + kt) << 12) + nt * 256 + lane * 8;
        *(uint2*)(base + off) = make_uint2(h0, h1);
    }
}

// ---------------------------------------------------------------------------
// fp16 HMMA GEMM on pre-split tiles. USE_LO: A has hi+lo parts (2-term),
// single-chunk loop. !USE_LO: 1-term, paired-chunk loop (1 barrier / 2 chunks,
// fragment registers reused between the two halves).
// 256 threads, 128x128 tile, BK=16, 4-stage cp.async ring, 2 CTAs/SM.
// ---------------------------------------------------------------------------
template <bool USE_LO>
__global__ __launch_bounds__(256, 2) void gemm_f16(
    const uint4* __restrict__ As, const uint4* __restrict__ Bs,
    float* __restrict__ C, __half* __restrict__ Ch,
    int M, int N, int K, const float* __restrict__ bias, int relu_limit)
{
    constexpr int ACH = USE_LO ? 8192 : 4096;   // A chunk bytes in gmem
    constexpr int STG = USE_LO ? 12288 : 8192;  // stage bytes in smem
    constexpr int BOFF = USE_LO ? 8192 : 4096;  // B offset within stage

    __shared__ char smem[4 * STG];

    const int tid  = threadIdx.x;
    const int lane = tid & 31;
    const int warp = tid >> 5;
    const int mb   = blockIdx.y;
    const int nb   = blockIdx.x;
    const int NKT  = K >> 4;
    const uint32_t sb = smem_u32(smem);

    const char* Abase = (const char*)As + (size_t)mb * NKT * ACH;
    const char* Bbase = (const char*)Bs + ((size_t)nb * NKT << 12);

    auto issue = [&](int kc) {
        const char* asrc = Abase + (size_t)kc * ACH;
        const char* bsrc = Bbase + ((size_t)kc << 12);
        const uint32_t dst0 = sb + (kc & 3) * STG;
#pragma unroll
        for (int i = 0; i < (USE_LO ? 2 : 1); i++) {
            const int c = tid + i * 256;
            asm volatile("cp.async.ca.shared.global [%0], [%1], 16;"
                         :: "r"(dst0 + c * 16), "l"(asrc + c * 16));
        }
        asm volatile("cp.async.ca.shared.global [%0], [%1], 16;"
                     :: "r"(dst0 + BOFF + tid * 16), "l"(bsrc + tid * 16));
        asm volatile("cp.async.commit_group;");
    };

    float4 acc[4][4];
#pragma unroll
    for (int i = 0; i < 4; i++)
#pragma unroll
        for (int j = 0; j < 4; j++) acc[i][j] = make_float4(0.f, 0.f, 0.f, 0.f);

    const int wm = (warp >> 2) * 4;   // A m-tile base (of 8)
    const int wn = (warp & 3) * 4;    // B n-tile base (of 16)

    // process one chunk's fragments + MMAs (regs reused across calls)
    auto do_chunk = [&](int kc) {
        const char* st = smem + (kc & 3) * STG;
        uint4 ah[4], al[4];
        uint2 bh[4];
#pragma unroll
        for (int mt = 0; mt < 4; mt++) {
            ah[mt] = *(const uint4*)(st + (wm + mt) * 512 + lane * 16);
            if (USE_LO)
                al[mt] = *(const uint4*)(st + 4096 + (wm + mt) * 512 + lane * 16);
        }
#pragma unroll
        for (int nt = 0; nt < 4; nt++)
            bh[nt] = *(const uint2*)(st + BOFF + (wn + nt) * 256 + lane * 8);
#pragma unroll
        for (int mt = 0; mt < 4; mt++)
#pragma unroll
            for (int nt = 0; nt < 4; nt++) mma16(acc[mt][nt], ah[mt], bh[nt]);
        if (USE_LO) {
#pragma unroll
            for (int mt = 0; mt < 4; mt++)
#pragma unroll
                for (int nt = 0; nt < 4; nt++) mma16(acc[mt][nt], al[mt], bh[nt]);
        }
    };

    if (USE_LO) {
        issue(0); issue(1); issue(2);
#pragma unroll 1
        for (int kc = 0; kc < NKT; kc++) {
            const int remain = NKT - 1 - kc;
            if (remain >= 2)      asm volatile("cp.async.wait_group 2;" ::: "memory");
            else if (remain == 1) asm volatile("cp.async.wait_group 1;" ::: "memory");
            else                  asm volatile("cp.async.wait_group 0;" ::: "memory");
            __syncthreads();
            if (kc + 3 < NKT) issue(kc + 3);
            do_chunk(kc);
        }
    } else {
        issue(0); issue(1); issue(2); issue(3);
#pragma unroll 1
        for (int kc = 0; kc < NKT; kc += 2) {
            if (kc + 2 >= NKT) asm volatile("cp.async.wait_group 0;" ::: "memory");
            else               asm volatile("cp.async.wait_group 2;" ::: "memory");
            __syncthreads();
            do_chunk(kc);
            do_chunk(kc + 1);
            __syncthreads();
            if (kc + 4 < NKT) issue(kc + 4);
            if (kc + 5 < NKT) issue(kc + 5);
        }
    }

    // epilogue: d0:(r,c) d1:(r,c+1) d2:(r+8,c) d3:(r+8,c+1); r=lane/4, c=2*(lane%4)
    const int rbase = mb * 128 + (warp >> 2) * 64 + (lane >> 2);
    const int cbase = nb * 128 + (warp & 3) * 32 + (lane & 3) * 2;
#pragma unroll
    for (int mt = 0; mt < 4; mt++) {
#pragma unroll
        for (int nt = 0; nt < 4; nt++) {
            const int r = rbase + mt * 16;
            const int c = cbase + nt * 8;
            float4 d = acc[mt][nt];
            if (Ch) {
                if (c < relu_limit) {
                    d.x = fmaxf(d.x, 0.f); d.y = fmaxf(d.y, 0.f);
                    d.z = fmaxf(d.z, 0.f); d.w = fmaxf(d.w, 0.f);
                }
                *(__half2*)(Ch + (size_t)r * N + c) =
                    __float22half2_rn(make_float2(d.x, d.y));
                *(__half2*)(Ch + (size_t)(r + 8) * N + c) =
                    __float22half2_rn(make_float2(d.z, d.w));
            } else {
                if (bias) {
                    float2 bb = *(const float2*)(bias + c);
                    d.x += bb.x; d.y += bb.y; d.z += bb.x; d.w += bb.y;
                }
                *(float2*)(C + (size_t)r * N + c)       = make_float2(d.x, d.y);
                *(float2*)(C + (size_t)(r + 8) * N + c) = make_float2(d.z, d.w);
            }
        }
    }
}

// ---------------------------------------------------------------------------
// KV partial: grid (96, 7); chunk c covers s in [c*448, c*448+448).
// k,v read as fp16, accumulated in fp32.
// ---------------------------------------------------------------------------
__global__ __launch_bounds__(256) void kv_part()
{
    const int bh = blockIdx.x;
    const int pc = blockIdx.y;
    const int b  = bh / 12;
    const int h  = bh % 12;

    __shared__ float Ks[64][64];
    __shared__ float Vs[64][64];

    const int tid = threadIdx.x;
    const int er  = tid >> 4;
    const int dg  = tid & 15;
    const int sl  = tid >> 2;
    const int ch  = tid & 3;

    float4 acc0 = {0,0,0,0}, acc1 = {0,0,0,0}, acc2 = {0,0,0,0}, acc3 = {0,0,0,0};
    float4 ksum = {0,0,0,0};

    const size_t base_k = (size_t)(b * 3136) * 2304 + 768  + h * 64;
    const size_t base_v = (size_t)(b * 3136) * 2304 + 1536 + h * 64;
    const int s_lo = pc * 448, s_hi = s_lo + 448;

    for (int s0 = s_lo; s0 < s_hi; s0 += 64) {
        const __half* kp = g_qkv + base_k + (size_t)(s0 + sl) * 2304 + ch * 16;
        const __half* vp = g_qkv + base_v + (size_t)(s0 + sl) * 2304 + ch * 16;
#pragma unroll
        for (int c = 0; c < 2; c++) {
            uint4 kr = *(const uint4*)(kp + c * 8);
            uint4 vr = *(const uint4*)(vp + c * 8);
            float2 f;
            f = __half22float2(*(__half2*)&kr.x); Ks[sl][ch*16 + c*8 + 0] = f.x; Ks[sl][ch*16 + c*8 + 1] = f.y;
            f = __half22float2(*(__half2*)&kr.y); Ks[sl][ch*16 + c*8 + 2] = f.x; Ks[sl][ch*16 + c*8 + 3] = f.y;
            f = __half22float2(*(__half2*)&kr.z); Ks[sl][ch*16 + c*8 + 4] = f.x; Ks[sl][ch*16 + c*8 + 5] = f.y;
            f = __half22float2(*(__half2*)&kr.w); Ks[sl][ch*16 + c*8 + 6] = f.x; Ks[sl][ch*16 + c*8 + 7] = f.y;
            f = __half22float2(*(__half2*)&vr.x); Vs[sl][ch*16 + c*8 + 0] = f.x; Vs[sl][ch*16 + c*8 + 1] = f.y;
            f = __half22float2(*(__half2*)&vr.y); Vs[sl][ch*16 + c*8 + 2] = f.x; Vs[sl][ch*16 + c*8 + 3] = f.y;
            f = __half22float2(*(__half2*)&vr.z); Vs[sl][ch*16 + c*8 + 4] = f.x; Vs[sl][ch*16 + c*8 + 5] = f.y;
            f = __half22float2(*(__half2*)&vr.w); Vs[sl][ch*16 + c*8 + 6] = f.x; Vs[sl][ch*16 + c*8 + 7] = f.y;
        }
        __syncthreads();

#pragma unroll 8
        for (int s = 0; s < 64; s++) {
            float4 k4 = *(const float4*)&Ks[s][er * 4];
            float4 v4 = *(const float4*)&Vs[s][dg * 4];
            acc0.x += k4.x * v4.x; acc0.y += k4.x * v4.y; acc0.z += k4.x * v4.z; acc0.w += k4.x * v4.w;
            acc1.x += k4.y * v4.x; acc1.y += k4.y * v4.y; acc1.z += k4.y * v4.z; acc1.w += k4.y * v4.w;
            acc2.x += k4.z * v4.x; acc2.y += k4.z * v4.y; acc2.z += k4.z * v4.z; acc2.w += k4.z * v4.w;
            acc3.x += k4.w * v4.x; acc3.y += k4.w * v4.y; acc3.z += k4.w * v4.z; acc3.w += k4.w * v4.w;
            if (dg == 0) {
                ksum.x += k4.x; ksum.y += k4.y; ksum.z += k4.z; ksum.w += k4.w;
            }
        }
        __syncthreads();
    }

    float* kvp = g_kvp + (size_t)(pc * 96 + bh) * 4096;
    *(float4*)&kvp[(er * 4 + 0) * 64 + dg * 4] = acc0;
    *(float4*)&kvp[(er * 4 + 1) * 64 + dg * 4] = acc1;
    *(float4*)&kvp[(er * 4 + 2) * 64 + dg * 4] = acc2;
    *(float4*)&kvp[(er * 4 + 3) * 64 + dg * 4] = acc3;
    if (dg == 0) *(float4*)&g_ksump[(pc * 96 + bh) * 64 + er * 4] = ksum;
}

// ---------------------------------------------------------------------------
// Reduce 7 partials (fixed order) + emit kv as fp16 hi/lo B-fragments.
// ---------------------------------------------------------------------------
__global__ __launch_bounds__(256) void kv_reduce()
{
    const int bh = blockIdx.x;
    const int tid = threadIdx.x;
    __shared__ float kvb[4096];

#pragma unroll 1
    for (int i = tid * 4; i < 4096; i += 1024) {
        float4 s = make_float4(0.f, 0.f, 0.f, 0.f);
#pragma unroll
        for (int p = 0; p < 7; p++) {
            float4 v = *(const float4*)&g_kvp[(size_t)(p * 96 + bh) * 4096 + i];
            s.x += v.x; s.y += v.y; s.z += v.z; s.w += v.w;
        }
        *(float4*)&kvb[i] = s;
    }
    if (tid < 64) {
        float s = 0.f;
#pragma unroll
        for (int p = 0; p < 7; p++) s += g_ksump[(p * 96 + bh) * 64 + tid];
        g_ksum[bh * 64 + tid] = s;
    }
    __syncthreads();

    // B-frag layout: [part(2)][kc(4)][nt(8)][lane(32)] uint2
    char* dst = (char*)g_kvfrag + (size_t)bh * 16384;
#pragma unroll
    for (int pos = tid; pos < 1024; pos += 256) {
        const int kc = pos >> 8, nt = (pos >> 5) & 7, ln = pos & 31;
        const int e0 = kc * 16 + 2 * (ln & 3);
        const int n  = nt * 8 + (ln >> 2);
        float v0 = kvb[e0 * 64 + n],       v1 = kvb[(e0 + 1) * 64 + n];
        float v2 = kvb[(e0 + 8) * 64 + n], v3 = kvb[(e0 + 9) * 64 + n];
        uint32_t l0, l1;
        uint32_t h0 = split2h(make_float2(v0, v1), l0);
        uint32_t h1 = split2h(make_float2(v2, v3), l1);
        *(uint2*)(dst + pos * 8)        = make_uint2(h0, h1);
        *(uint2*)(dst + 8192 + pos * 8) = make_uint2(l0, l1);
    }
}

// ---------------------------------------------------------------------------
// vo_gemm: per (bh, 64-token tile): out = (q @ kv) * z, z = 1/(q.ksum+eps),
// written directly as fp16 hi/lo fragments into g_a2s.
// ---------------------------------------------------------------------------
__global__ __launch_bounds__(128) void vo_gemm()
{
    const int bh   = blockIdx.x;
    const int tile = blockIdx.y;      // 0..48
    const int b = bh / 12, h = bh % 12;

    __shared__ char bfr[16384];
    __shared__ float ks[64];

    const int tid = threadIdx.x, lane = tid & 31, warp = tid >> 5;
    const uint32_t sb = smem_u32(bfr);

    const char* src = (const char*)g_kvfrag + (size_t)bh * 16384;
#pragma unroll
    for (int i = 0; i < 8; i++) {
        const int c = tid + i * 128;
        asm volatile("cp.async.ca.shared.global [%0], [%1], 16;"
                     :: "r"(sb + c * 16), "l"(src + c * 16));
    }
    asm volatile("cp.async.commit_group;");
    if (tid < 64) ks[tid] = g_ksum[bh * 64 + tid];
    asm volatile("cp.async.wait_group 0;" ::: "memory");
    __syncthreads();

    const int r  = lane >> 2;
    const int c2 = 2 * (lane & 3);
    const size_t tok0 = (size_t)b * 3136 + tile * 64 + warp * 16;
    const __half* qbase = g_qkv + tok0 * 2304 + h * 64;

    uint32_t a[4][4];
    float dr = 0.f, dr8 = 0.f;
#pragma unroll
    for (int kc = 0; kc < 4; kc++) {
        const int e0 = kc * 16 + c2;
        a[kc][0] = *(const uint32_t*)(qbase + (size_t)r * 2304 + e0);
        a[kc][1] = *(const uint32_t*)(qbase + (size_t)(r + 8) * 2304 + e0);
        a[kc][2] = *(const uint32_t*)(qbase + (size_t)r * 2304 + e0 + 8);
        a[kc][3] = *(const uint32_t*)(qbase + (size_t)(r + 8) * 2304 + e0 + 8);
        float2 f0 = __half22float2(*(__half2*)&a[kc][0]);
        float2 f1 = __half22float2(*(__half2*)&a[kc][1]);
        float2 f2 = __half22float2(*(__half2*)&a[kc][2]);
        float2 f3 = __half22float2(*(__half2*)&a[kc][3]);
        dr  += f0.x * ks[e0] + f0.y * ks[e0 + 1] + f2.x * ks[e0 + 8] + f2.y * ks[e0 + 9];
        dr8 += f1.x * ks[e0] + f1.y * ks[e0 + 1] + f3.x * ks[e0 + 8] + f3.y * ks[e0 + 9];
    }
    dr  += __shfl_xor_sync(FULL_MASK, dr, 1);  dr  += __shfl_xor_sync(FULL_MASK, dr, 2);
    dr8 += __shfl_xor_sync(FULL_MASK, dr8, 1); dr8 += __shfl_xor_sync(FULL_MASK, dr8, 2);
    const float zr  = 1.0f / (dr + 1e-4f);
    const float zr8 = 1.0f / (dr8 + 1e-4f);

    float4 acc[8];
#pragma unroll
    for (int nt = 0; nt < 8; nt++) acc[nt] = make_float4(0.f, 0.f, 0.f, 0.f);

#pragma unroll
    for (int part = 0; part < 2; part++) {
#pragma unroll
        for (int kc = 0; kc < 4; kc++) {
            const char* pb = bfr + part * 8192 + kc * 2048;
            uint4 av = make_uint4(a[kc][0], a[kc][1], a[kc][2], a[kc][3]);
#pragma unroll
            for (int nt = 0; nt < 8; nt++) {
                uint2 bb = *(const uint2*)(pb + nt * 256 + lane * 8);
                mma16(acc[nt], av, bb);
            }
        }
    }

    const int mb = (int)(tok0 >> 7);
    const int mt = ((int)tok0 >> 4) & 7;
    char* abase = (char*)g_a2s;
#pragma unroll
    for (int nt = 0; nt < 8; nt++) {
        const int kt = h * 4 + (nt >> 1);
        char* p = abase + (((size_t)(mb * 48 + kt)) << 13) + mt * 512 + lane * 16 + (nt & 1) * 8;
        uint32_t lo;
        uint32_t hi = split2h(make_float2(acc[nt].x * zr, acc[nt].y * zr), lo);
        *(uint32_t*)p          = hi;
        *(uint32_t*)(p + 4096) = lo;
        hi = split2h(make_float2(acc[nt].z * zr8, acc[nt].w * zr8), lo);
        *(uint32_t*)(p + 4)        = hi;
        *(uint32_t*)(p + 4096 + 4) = lo;
    }
}

// ---------------------------------------------------------------------------
extern "C" void kernel_launch(void* const* d_in, const int* in_sizes, int n_in,
                              void* d_out, int out_size)
{
    const float* x     = (const float*)d_in[0];
    const float* Wqkv  = (const float*)d_in[1];
    const float* Wproj = (const float*)d_in[2];
    const float* bproj = (const float*)d_in[3];
    float* out = (float*)d_out;

    __half* qkv_p;
    uint4 *a1s, *a2s, *b1s, *b2s;
    cudaGetSymbolAddress((void**)&qkv_p, g_qkv);
    cudaGetSymbolAddress((void**)&a1s, g_a1s);
    cudaGetSymbolAddress((void**)&a2s, g_a2s);
    cudaGetSymbolAddress((void**)&b1s, g_b1s);
    cudaGetSymbolAddress((void**)&b2s, g_b2s);

    // 0) pre-split weights + input into fp16 fragment tiles
    split_b<<<2304 / 8, 256>>>(Wqkv,  b1s, 768);
    split_b<<<768 / 8, 256>>>(Wproj, b2s, 768);
    split_a<<<M_TOK / 16, 256>>>(x, a1s, 768);

    // 1) qkv = x @ Wqkv^T -> fp16 (1-term A, paired-chunk loop, fused ReLU)
    gemm_f16<false><<<dim3(2304 / 128, M_TOK / 128), 256>>>(
        a1s, b1s, nullptr, qkv_p, M_TOK, 2304, 768, nullptr, 1536);

    // 2) kv and k_sum per (b,h): S-split partials + reduce (+ kv frag emit)
    kv_part<<<dim3(96, 7), 256>>>();
    kv_reduce<<<96, 256>>>();

    // 3) out = (q @ kv) * z as tensor-core GEMM -> fp16 hi/lo fragments
    vo_gemm<<<dim3(96, 49), 128>>>();

    // 4) out = attn @ Wproj^T + bproj (2-term A, fp32 out)
    gemm_f16<true><<<dim3(768 / 128, M_TOK / 128), 256>>>(
        a2s, b2s, out, nullptr, M_TOK, 768, 768, bproj, 0);
}

// round 13
// speedup vs baseline: 2.1803x; 1.1189x over previous
#include <cuda_runtime.h>
#include <cuda_fp16.h>
#include <cstdint>
#include <cstddef>

#define FULL_MASK 0xFFFFFFFFu

// Problem constants: B=128, N=196, C=768, h=12, e=64, frames=16
// tokens M = 25088 ; b = 8 ; S = 3136 ; bh = 96
static const int M_TOK = 25088;

// ---------------------------------------------------------------------------
// Scratch (allocation-free: __device__ globals)
// ---------------------------------------------------------------------------
__device__ __half g_qkv[(size_t)25088 * 2304]; // [tok][3*C] (q|k|v) fp16, q/k ReLU'd
__device__ float g_ksum[96 * 64];               // [bh][e]
__device__ float g_kvp[7 * 96 * 64 * 64];       // S-split partials
__device__ float g_ksump[7 * 96 * 64];
__device__ uint2 g_kvfrag[96 * 2048];           // [bh][part(2)][kc(4)][nt(8)][lane(32)] uint2

// fp16 fragment-ordered tiles (hi only).
// A: [mb][kt][mtile(8)][512B] -> chunk 4KB ; B: [nb][kt][ntile(16)][256B] -> 4KB
__device__ uint4 g_a1s[(25088 / 16) * (768 / 16) * 32];   // 38.5 MB (x)
__device__ uint4 g_a2s[(25088 / 16) * (768 / 16) * 32];   // 38.5 MB (attn, by vo_gemm)
__device__ uint4 g_b1s[(2304 / 8) * (768 / 16) * 16];     // 3.5 MB (Wqkv)
__device__ uint4 g_b2s[(768 / 8) * (768 / 16) * 16];      // 1.2 MB (Wproj)

// ---------------------------------------------------------------------------
__device__ __forceinline__ uint32_t smem_u32(const void* p) {
    uint32_t r;
    asm("{.reg .u64 t; cvta.to.shared.u64 t, %1; cvt.u32.u64 %0, t;}" : "=r"(r) : "l"(p));
    return r;
}

// Split float2 -> hi f16x2 (return) + residual f16x2 (lo). low half = .x
__device__ __forceinline__ uint32_t split2h(float2 v, uint32_t& lo) {
    __half2 h = __float22half2_rn(v);
    float2 back = __half22float2(h);
    __half2 l = __float22half2_rn(make_float2(v.x - back.x, v.y - back.y));
    lo = *(uint32_t*)&l;
    return *(uint32_t*)&h;
}
__device__ __forceinline__ uint32_t cvt2h(float2 v) {
    __half2 h = __float22half2_rn(v);
    return *(uint32_t*)&h;
}

// mma.sync m16n8k16 fp16: d += a*b (row.col, f32 accum)
__device__ __forceinline__ void mma16(float4& d, uint4 a, uint2 b) {
    asm volatile(
        "mma.sync.aligned.m16n8k16.row.col.f32.f16.f16.f32 "
        "{%0,%1,%2,%3}, {%4,%5,%6,%7}, {%8,%9}, {%0,%1,%2,%3};"
        : "+f"(d.x), "+f"(d.y), "+f"(d.z), "+f"(d.w)
        : "r"(a.x), "r"(a.y), "r"(a.z), "r"(a.w), "r"(b.x), "r"(b.y));
}

// ---------------------------------------------------------------------------
// split_a: fp32 [M][K] -> A-frag tiles (hi fp16), m16n8k16 A layout.
// ---------------------------------------------------------------------------
__global__ __launch_bounds__(256) void split_a(const float* __restrict__ src,
                                               uint4* __restrict__ dst, int K)
{
    const int NKT  = K >> 4;
    const int strip = blockIdx.x;
    const int warp = threadIdx.x >> 5, lane = threadIdx.x & 31;
    const int mb = strip >> 3, mt = strip & 7;
    const int c2 = (lane & 3) * 2;
    const float* row0 = src + (size_t)(strip * 16 + (lane >> 2)) * K;
    const float* row1 = row0 + (size_t)8 * K;
    char* base = (char*)dst;

    for (int kt = warp; kt < NKT; kt += 8) {
        const int kb = kt * 16;
        uint32_t h0 = cvt2h(*(const float2*)(row0 + kb + c2));
        uint32_t h1 = cvt2h(*(const float2*)(row1 + kb + c2));
        uint32_t h2 = cvt2h(*(const float2*)(row0 + kb + c2 + 8));
        uint32_t h3 = cvt2h(*(const float2*)(row1 + kb + c2 + 8));
        size_t off = ((size_t)(mb * NKT + kt) << 12) + mt * 512 + lane * 16;
        *(uint4*)(base + off) = make_uint4(h0, h1, h2, h3);
    }
}

// ---------------------------------------------------------------------------
// split_b: fp32 [N][K] -> B-frag tiles (hi fp16), m16n8k16 B layout.
// ---------------------------------------------------------------------------
__global__ __launch_bounds__(256) void split_b(const float* __restrict__ src,
                                               uint4* __restrict__ dst, int K)
{
    const int NKT  = K >> 4;
    const int strip = blockIdx.x;
    const int warp = threadIdx.x >> 5, lane = threadIdx.x & 31;
    const int nb = strip >> 4, nt = strip & 15;
    const int c2 = (lane & 3) * 2;
    const float* row = src + (size_t)(strip * 8 + (lane >> 2)) * K;
    char* base = (char*)dst;

    for (int kt = warp; kt < NKT; kt += 8) {
        const int kb = kt * 16;
        uint32_t h0 = cvt2h(*(const float2*)(row + kb + c2));
        uint32_t h1 = cvt2h(*(const float2*)(row + kb + c2 + 8));
        size_t off = ((size_t)(nb * NKT + kt) << 12) + nt * 256 + lane * 8;
        *(uint2*)(base + off) = make_uint2(h0, h1);
    }
}

// ---------------------------------------------------------------------------
// fp16 1-term HMMA GEMM on pre-split tiles. Paired-chunk loop (1 barrier per
// 2 chunks, frag regs reused). 256 threads, 128x128 tile, BK=16, 4-stage
// cp.async ring, 2 CTAs/SM. Output: half (Ch, ReLU<relu_limit) or fp32 (C,+bias).
// ---------------------------------------------------------------------------
__global__ __launch_bounds__(256, 2) void gemm_f16(
    const uint4* __restrict__ As, const uint4* __restrict__ Bs,
    float* __restrict__ C, __half* __restrict__ Ch,
    int M, int N, int K, const float* __restrict__ bias, int relu_limit)
{
    __shared__ char smem[4 * 8192];

    const int tid  = threadIdx.x;
    const int lane = tid & 31;
    const int warp = tid >> 5;
    const int mb   = blockIdx.y;
    const int nb   = blockIdx.x;
    const int NKT  = K >> 4;          // 48 (even)
    const uint32_t sb = smem_u32(smem);

    const char* Abase = (const char*)As + ((size_t)mb * NKT << 12);
    const char* Bbase = (const char*)Bs + ((size_t)nb * NKT << 12);

    auto issue = [&](int kc) {
        const char* asrc = Abase + ((size_t)kc << 12);
        const char* bsrc = Bbase + ((size_t)kc << 12);
        const uint32_t dst0 = sb + (kc & 3) * 8192;
        asm volatile("cp.async.ca.shared.global [%0], [%1], 16;"
                     :: "r"(dst0 + tid * 16), "l"(asrc + tid * 16));
        asm volatile("cp.async.ca.shared.global [%0], [%1], 16;"
                     :: "r"(dst0 + 4096 + tid * 16), "l"(bsrc + tid * 16));
        asm volatile("cp.async.commit_group;");
    };

    float4 acc[4][4];
#pragma unroll
    for (int i = 0; i < 4; i++)
#pragma unroll
        for (int j = 0; j < 4; j++) acc[i][j] = make_float4(0.f, 0.f, 0.f, 0.f);

    const int wm = (warp >> 2) * 4;   // A m-tile base (of 8)
    const int wn = (warp & 3) * 4;    // B n-tile base (of 16)

    auto do_chunk = [&](int kc) {
        const char* st = smem + (kc & 3) * 8192;
        uint4 ah[4];
        uint2 bh[4];
#pragma unroll
        for (int mt = 0; mt < 4; mt++)
            ah[mt] = *(const uint4*)(st + (wm + mt) * 512 + lane * 16);
#pragma unroll
        for (int nt = 0; nt < 4; nt++)
            bh[nt] = *(const uint2*)(st + 4096 + (wn + nt) * 256 + lane * 8);
#pragma unroll
        for (int mt = 0; mt < 4; mt++)
#pragma unroll
            for (int nt = 0; nt < 4; nt++) mma16(acc[mt][nt], ah[mt], bh[nt]);
    };

    issue(0); issue(1); issue(2); issue(3);
#pragma unroll 1
    for (int kc = 0; kc < NKT; kc += 2) {
        if (kc + 2 >= NKT) asm volatile("cp.async.wait_group 0;" ::: "memory");
        else               asm volatile("cp.async.wait_group 2;" ::: "memory");
        __syncthreads();
        do_chunk(kc);
        do_chunk(kc + 1);
        __syncthreads();
        if (kc + 4 < NKT) issue(kc + 4);
        if (kc + 5 < NKT) issue(kc + 5);
    }

    // epilogue: d0:(r,c) d1:(r,c+1) d2:(r+8,c) d3:(r+8,c+1); r=lane/4, c=2*(lane%4)
    const int rbase = mb * 128 + (warp >> 2) * 64 + (lane >> 2);
    const int cbase = nb * 128 + (warp & 3) * 32 + (lane & 3) * 2;
#pragma unroll
    for (int mt = 0; mt < 4; mt++) {
#pragma unroll
        for (int nt = 0; nt < 4; nt++) {
            const int r = rbase + mt * 16;
            const int c = cbase + nt * 8;
            float4 d = acc[mt][nt];
            if (Ch) {
                if (c < relu_limit) {
                    d.x = fmaxf(d.x, 0.f); d.y = fmaxf(d.y, 0.f);
                    d.z = fmaxf(d.z, 0.f); d.w = fmaxf(d.w, 0.f);
                }
                *(__half2*)(Ch + (size_t)r * N + c) =
                    __float22half2_rn(make_float2(d.x, d.y));
                *(__half2*)(Ch + (size_t)(r + 8) * N + c) =
                    __float22half2_rn(make_float2(d.z, d.w));
            } else {
                if (bias) {
                    float2 bb = *(const float2*)(bias + c);
                    d.x += bb.x; d.y += bb.y; d.z += bb.x; d.w += bb.y;
                }
                *(float2*)(C + (size_t)r * N + c)       = make_float2(d.x, d.y);
                *(float2*)(C + (size_t)(r + 8) * N + c) = make_float2(d.z, d.w);
            }
        }
    }
}

// ---------------------------------------------------------------------------
// KV partial: grid (96, 7); chunk c covers s in [c*448, c*448+448).
// k,v read as fp16, accumulated in fp32.
// ---------------------------------------------------------------------------
__global__ __launch_bounds__(256) void kv_part()
{
    const int bh = blockIdx.x;
    const int pc = blockIdx.y;
    const int b  = bh / 12;
    const int h  = bh % 12;

    __shared__ float Ks[64][64];
    __shared__ float Vs[64][64];

    const int tid = threadIdx.x;
    const int er  = tid >> 4;
    const int dg  = tid & 15;
    const int sl  = tid >> 2;
    const int ch  = tid & 3;

    float4 acc0 = {0,0,0,0}, acc1 = {0,0,0,0}, acc2 = {0,0,0,0}, acc3 = {0,0,0,0};
    float4 ksum = {0,0,0,0};

    const size_t base_k = (size_t)(b * 3136) * 2304 + 768  + h * 64;
    const size_t base_v = (size_t)(b * 3136) * 2304 + 1536 + h * 64;
    const int s_lo = pc * 448, s_hi = s_lo + 448;

    for (int s0 = s_lo; s0 < s_hi; s0 += 64) {
        const __half* kp = g_qkv + base_k + (size_t)(s0 + sl) * 2304 + ch * 16;
        const __half* vp = g_qkv + base_v + (size_t)(s0 + sl) * 2304 + ch * 16;
#pragma unroll
        for (int c = 0; c < 2; c++) {
            uint4 kr = *(const uint4*)(kp + c * 8);
            uint4 vr = *(const uint4*)(vp + c * 8);
            float2 f;
            f = __half22float2(*(__half2*)&kr.x); Ks[sl][ch*16 + c*8 + 0] = f.x; Ks[sl][ch*16 + c*8 + 1] = f.y;
            f = __half22float2(*(__half2*)&kr.y); Ks[sl][ch*16 + c*8 + 2] = f.x; Ks[sl][ch*16 + c*8 + 3] = f.y;
            f = __half22float2(*(__half2*)&kr.z); Ks[sl][ch*16 + c*8 + 4] = f.x; Ks[sl][ch*16 + c*8 + 5] = f.y;
            f = __half22float2(*(__half2*)&kr.w); Ks[sl][ch*16 + c*8 + 6] = f.x; Ks[sl][ch*16 + c*8 + 7] = f.y;
            f = __half22float2(*(__half2*)&vr.x); Vs[sl][ch*16 + c*8 + 0] = f.x; Vs[sl][ch*16 + c*8 + 1] = f.y;
            f = __half22float2(*(__half2*)&vr.y); Vs[sl][ch*16 + c*8 + 2] = f.x; Vs[sl][ch*16 + c*8 + 3] = f.y;
            f = __half22float2(*(__half2*)&vr.z); Vs[sl][ch*16 + c*8 + 4] = f.x; Vs[sl][ch*16 + c*8 + 5] = f.y;
            f = __half22float2(*(__half2*)&vr.w); Vs[sl][ch*16 + c*8 + 6] = f.x; Vs[sl][ch*16 + c*8 + 7] = f.y;
        }
        __syncthreads();

#pragma unroll 8
        for (int s = 0; s < 64; s++) {
            float4 k4 = *(const float4*)&Ks[s][er * 4];
            float4 v4 = *(const float4*)&Vs[s][dg * 4];
            acc0.x += k4.x * v4.x; acc0.y += k4.x * v4.y; acc0.z += k4.x * v4.z; acc0.w += k4.x * v4.w;
            acc1.x += k4.y * v4.x; acc1.y += k4.y * v4.y; acc1.z += k4.y * v4.z; acc1.w += k4.y * v4.w;
            acc2.x += k4.z * v4.x; acc2.y += k4.z * v4.y; acc2.z += k4.z * v4.z; acc2.w += k4.z * v4.w;
            acc3.x += k4.w * v4.x; acc3.y += k4.w * v4.y; acc3.z += k4.w * v4.z; acc3.w += k4.w * v4.w;
            if (dg == 0) {
                ksum.x += k4.x; ksum.y += k4.y; ksum.z += k4.z; ksum.w += k4.w;
            }
        }
        __syncthreads();
    }

    float* kvp = g_kvp + (size_t)(pc * 96 + bh) * 4096;
    *(float4*)&kvp[(er * 4 + 0) * 64 + dg * 4] = acc0;
    *(float4*)&kvp[(er * 4 + 1) * 64 + dg * 4] = acc1;
    *(float4*)&kvp[(er * 4 + 2) * 64 + dg * 4] = acc2;
    *(float4*)&kvp[(er * 4 + 3) * 64 + dg * 4] = acc3;
    if (dg == 0) *(float4*)&g_ksump[(pc * 96 + bh) * 64 + er * 4] = ksum;
}

// ---------------------------------------------------------------------------
// Reduce 7 partials (fixed order) + emit kv as fp16 hi/lo B-fragments.
// ---------------------------------------------------------------------------
__global__ __launch_bounds__(256) void kv_reduce()
{
    const int bh = blockIdx.x;
    const int tid = threadIdx.x;
    __shared__ float kvb[4096];

#pragma unroll 1
    for (int i = tid * 4; i < 4096; i += 1024) {
        float4 s = make_float4(0.f, 0.f, 0.f, 0.f);
#pragma unroll
        for (int p = 0; p < 7; p++) {
            float4 v = *(const float4*)&g_kvp[(size_t)(p * 96 + bh) * 4096 + i];
            s.x += v.x; s.y += v.y; s.z += v.z; s.w += v.w;
        }
        *(float4*)&kvb[i] = s;
    }
    if (tid < 64) {
        float s = 0.f;
#pragma unroll
        for (int p = 0; p < 7; p++) s += g_ksump[(p * 96 + bh) * 64 + tid];
        g_ksum[bh * 64 + tid] = s;
    }
    __syncthreads();

    // B-frag layout: [part(2)][kc(4)][nt(8)][lane(32)] uint2
    char* dst = (char*)g_kvfrag + (size_t)bh * 16384;
#pragma unroll
    for (int pos = tid; pos < 1024; pos += 256) {
        const int kc = pos >> 8, nt = (pos >> 5) & 7, ln = pos & 31;
        const int e0 = kc * 16 + 2 * (ln & 3);
        const int n  = nt * 8 + (ln >> 2);
        float v0 = kvb[e0 * 64 + n],       v1 = kvb[(e0 + 1) * 64 + n];
        float v2 = kvb[(e0 + 8) * 64 + n], v3 = kvb[(e0 + 9) * 64 + n];
        uint32_t l0, l1;
        uint32_t h0 = split2h(make_float2(v0, v1), l0);
        uint32_t h1 = split2h(make_float2(v2, v3), l1);
        *(uint2*)(dst + pos * 8)        = make_uint2(h0, h1);
        *(uint2*)(dst + 8192 + pos * 8) = make_uint2(l0, l1);
    }
}

// ---------------------------------------------------------------------------
// vo_gemm: per (bh, 64-token tile): out = (q @ kv) * z, z = 1/(q.ksum+eps),
// written directly as fp16 hi fragments into g_a2s.
// ---------------------------------------------------------------------------
__global__ __launch_bounds__(128) void vo_gemm()
{
    const int bh   = blockIdx.x;
    const int tile = blockIdx.y;      // 0..48
    const int b = bh / 12, h = bh % 12;

    __shared__ char bfr[16384];
    __shared__ float ks[64];

    const int tid = threadIdx.x, lane = tid & 31, warp = tid >> 5;
    const uint32_t sb = smem_u32(bfr);

    const char* src = (const char*)g_kvfrag + (size_t)bh * 16384;
#pragma unroll
    for (int i = 0; i < 8; i++) {
        const int c = tid + i * 128;
        asm volatile("cp.async.ca.shared.global [%0], [%1], 16;"
                     :: "r"(sb + c * 16), "l"(src + c * 16));
    }
    asm volatile("cp.async.commit_group;");
    if (tid < 64) ks[tid] = g_ksum[bh * 64 + tid];
    asm volatile("cp.async.wait_group 0;" ::: "memory");
    __syncthreads();

    const int r  = lane >> 2;
    const int c2 = 2 * (lane & 3);
    const size_t tok0 = (size_t)b * 3136 + tile * 64 + warp * 16;
    const __half* qbase = g_qkv + tok0 * 2304 + h * 64;

    uint32_t a[4][4];
    float dr = 0.f, dr8 = 0.f;
#pragma unroll
    for (int kc = 0; kc < 4; kc++) {
        const int e0 = kc * 16 + c2;
        a[kc][0] = *(const uint32_t*)(qbase + (size_t)r * 2304 + e0);
        a[kc][1] = *(const uint32_t*)(qbase + (size_t)(r + 8) * 2304 + e0);
        a[kc][2] = *(const uint32_t*)(qbase + (size_t)r * 2304 + e0 + 8);
        a[kc][3] = *(const uint32_t*)(qbase + (size_t)(r + 8) * 2304 + e0 + 8);
        float2 f0 = __half22float2(*(__half2*)&a[kc][0]);
        float2 f1 = __half22float2(*(__half2*)&a[kc][1]);
        float2 f2 = __half22float2(*(__half2*)&a[kc][2]);
        float2 f3 = __half22float2(*(__half2*)&a[kc][3]);
        dr  += f0.x * ks[e0] + f0.y * ks[e0 + 1] + f2.x * ks[e0 + 8] + f2.y * ks[e0 + 9];
        dr8 += f1.x * ks[e0] + f1.y * ks[e0 + 1] + f3.x * ks[e0 + 8] + f3.y * ks[e0 + 9];
    }
    dr  += __shfl_xor_sync(FULL_MASK, dr, 1);  dr  += __shfl_xor_sync(FULL_MASK, dr, 2);
    dr8 += __shfl_xor_sync(FULL_MASK, dr8, 1); dr8 += __shfl_xor_sync(FULL_MASK, dr8, 2);
    const float zr  = 1.0f / (dr + 1e-4f);
    const float zr8 = 1.0f / (dr8 + 1e-4f);

    float4 acc[8];
#pragma unroll
    for (int nt = 0; nt < 8; nt++) acc[nt] = make_float4(0.f, 0.f, 0.f, 0.f);

#pragma unroll
    for (int part = 0; part < 2; part++) {
#pragma unroll
        for (int kc = 0; kc < 4; kc++) {
            const char* pb = bfr + part * 8192 + kc * 2048;
            uint4 av = make_uint4(a[kc][0], a[kc][1], a[kc][2], a[kc][3]);
#pragma unroll
            for (int nt = 0; nt < 8; nt++) {
                uint2 bb = *(const uint2*)(pb + nt * 256 + lane * 8);
                mma16(acc[nt], av, bb);
            }
        }
    }

    // epilogue: hi-only fragment store into g_a2s
    const int mb = (int)(tok0 >> 7);
    const int mt = ((int)tok0 >> 4) & 7;
    char* abase = (char*)g_a2s;
#pragma unroll
    for (int nt = 0; nt < 8; nt++) {
        const int kt = h * 4 + (nt >> 1);
        char* p = abase + (((size_t)(mb * 48 + kt)) << 12) + mt * 512 + lane * 16 + (nt & 1) * 8;
        *(uint32_t*)p = cvt2h(make_float2(acc[nt].x * zr, acc[nt].y * zr));
        *(uint32_t*)(p + 4) = cvt2h(make_float2(acc[nt].z * zr8, acc[nt].w * zr8));
    }
}

// ---------------------------------------------------------------------------
extern "C" void kernel_launch(void* const* d_in, const int* in_sizes, int n_in,
                              void* d_out, int out_size)
{
    const float* x     = (const float*)d_in[0];
    const float* Wqkv  = (const float*)d_in[1];
    const float* Wproj = (const float*)d_in[2];
    const float* bproj = (const float*)d_in[3];
    float* out = (float*)d_out;

    __half* qkv_p;
    uint4 *a1s, *a2s, *b1s, *b2s;
    cudaGetSymbolAddress((void**)&qkv_p, g_qkv);
    cudaGetSymbolAddress((void**)&a1s, g_a1s);
    cudaGetSymbolAddress((void**)&a2s, g_a2s);
    cudaGetSymbolAddress((void**)&b1s, g_b1s);
    cudaGetSymbolAddress((void**)&b2s, g_b2s);

    // 0) pre-split weights + input into fp16 fragment tiles
    split_b<<<2304 / 8, 256>>>(Wqkv,  b1s, 768);
    split_b<<<768 / 8, 256>>>(Wproj, b2s, 768);
    split_a<<<M_TOK / 16, 256>>>(x, a1s, 768);

    // 1) qkv = x @ Wqkv^T -> fp16 (fused ReLU on q,k cols < 1536)
    gemm_f16<<<dim3(2304 / 128, M_TOK / 128), 256>>>(
        a1s, b1s, nullptr, qkv_p, M_TOK, 2304, 768, nullptr, 1536);

    // 2) kv and k_sum per (b,h): S-split partials + reduce (+ kv frag emit)
    kv_part<<<dim3(96, 7), 256>>>();
    kv_reduce<<<96, 256>>>();

    // 3) out = (q @ kv) * z as tensor-core GEMM -> fp16 hi fragments
    vo_gemm<<<dim3(96, 49), 128>>>();

    // 4) out = attn @ Wproj^T + bproj (fp32 out)
    gemm_f16<<<dim3(768 / 128, M_TOK / 128), 256>>>(
        a2s, b2s, out, nullptr, M_TOK, 768, 768, bproj, 0);
}